// round 2
// baseline (speedup 1.0000x reference)
#include <cuda_runtime.h>
#include <math.h>

// ---------------------------------------------------------------------------
// Problem constants
// ---------------------------------------------------------------------------
#define BATCH   16384
#define SEQ     8
#define MTOK    (BATCH * SEQ)     // 131072 token rows
#define DM      512
#define DH      2048
#define NHEAD   8
#define DK      64
#define LN_EPS  1e-6f

// ---------------------------------------------------------------------------
// Scratch (device globals: the sanctioned alloc-free workaround)
// ---------------------------------------------------------------------------
__device__ float g_h  [(size_t)MTOK * DM];   // activations
__device__ float g_q  [(size_t)MTOK * DM];
__device__ float g_k  [(size_t)MTOK * DM];
__device__ float g_v  [(size_t)MTOK * DM];
__device__ float g_t  [(size_t)MTOK * DM];   // gemm temp / attn ctx
__device__ float g_mid[(size_t)MTOK * DH];   // FFN hidden

// ---------------------------------------------------------------------------
// Packed f32x2 helpers (FFMA2: 2x fp32 FMA throughput vs scalar FFMA on B300)
// ---------------------------------------------------------------------------
__device__ __forceinline__ unsigned long long pk2(float lo, float hi) {
    unsigned long long r;
    asm("mov.b64 %0, {%1, %2};" : "=l"(r) : "f"(lo), "f"(hi));
    return r;
}
__device__ __forceinline__ unsigned long long dup2(float v) {
    unsigned long long r;
    asm("mov.b64 %0, {%1, %1};" : "=l"(r) : "f"(v));
    return r;
}
__device__ __forceinline__ void upk2(unsigned long long p, float& lo, float& hi) {
    asm("mov.b64 {%0, %1}, %2;" : "=f"(lo), "=f"(hi) : "l"(p));
}
__device__ __forceinline__ void ffma2(unsigned long long& d,
                                      unsigned long long a,
                                      unsigned long long b) {
    asm("fma.rn.f32x2 %0, %1, %2, %0;" : "+l"(d) : "l"(a), "l"(b));
}

// ---------------------------------------------------------------------------
// Positional encoding add: h = x + sinusoid(s, d)
// ---------------------------------------------------------------------------
__global__ void pos_kernel(const float* __restrict__ x, float* __restrict__ h) {
    int t = blockIdx.x * 256 + threadIdx.x;           // < MTOK*DM = 67108864
    int c = t & 511;
    int s = (t >> 9) & 7;
    int d2 = c >> 1;
    float e = (float)(2 * d2) * (1.0f / 512.0f);
    float ang = (float)s * powf(10000.0f, -e);
    float p = (c & 1) ? cosf(ang) : sinf(ang);
    h[t] = x[t] + p;
}

// ---------------------------------------------------------------------------
// Tiled SGEMM: C[M,N] = A[M,K] @ B[K,N] + bias (+optional ReLU)
// 128x128 tile, BK=8, 256 threads, 8x8 microtile, fp32x2 inner loop.
// All dims divide tiles exactly (M=131072, N in {512,2048}, K in {512,2048}).
// ---------------------------------------------------------------------------
__global__ __launch_bounds__(256)
void gemm_kernel(const float* __restrict__ A, const float* __restrict__ B,
                 const float* __restrict__ bias, float* __restrict__ C,
                 int N, int K, int relu) {
    __shared__ float As[8][128];
    __shared__ float Bs[8][128];

    const int tid  = threadIdx.x;
    const int m0   = blockIdx.y * 128;
    const int n0   = blockIdx.x * 128;
    const int arow = tid >> 1;
    const int acol = (tid & 1) << 2;
    const int brow = tid >> 5;
    const int bcol = (tid & 31) << 2;
    const int tx   = tid & 15;
    const int ty   = tid >> 4;

    const float* Ap = A + (size_t)(m0 + arow) * K + acol;
    const float* Bp = B + (size_t)brow * N + n0 + bcol;

    unsigned long long acc[8][4];
#pragma unroll
    for (int i = 0; i < 8; i++)
#pragma unroll
        for (int j = 0; j < 4; j++) acc[i][j] = 0ull;   // packed {0.f, 0.f}

    for (int k0 = 0; k0 < K; k0 += 8) {
        float4 av = *(const float4*)(Ap + k0);
        float4 bv = *(const float4*)(Bp + (size_t)k0 * N);
        As[acol + 0][arow] = av.x;
        As[acol + 1][arow] = av.y;
        As[acol + 2][arow] = av.z;
        As[acol + 3][arow] = av.w;
        *(float4*)&Bs[brow][bcol] = bv;
        __syncthreads();

#pragma unroll
        for (int kk = 0; kk < 8; kk++) {
            float4 a0 = *(const float4*)&As[kk][ty << 3];
            float4 a1 = *(const float4*)&As[kk][(ty << 3) + 4];
            float4 b0 = *(const float4*)&Bs[kk][tx << 3];
            float4 b1 = *(const float4*)&Bs[kk][(tx << 3) + 4];
            unsigned long long ad[8], bp[4];
            ad[0] = dup2(a0.x); ad[1] = dup2(a0.y);
            ad[2] = dup2(a0.z); ad[3] = dup2(a0.w);
            ad[4] = dup2(a1.x); ad[5] = dup2(a1.y);
            ad[6] = dup2(a1.z); ad[7] = dup2(a1.w);
            bp[0] = pk2(b0.x, b0.y); bp[1] = pk2(b0.z, b0.w);
            bp[2] = pk2(b1.x, b1.y); bp[3] = pk2(b1.z, b1.w);
#pragma unroll
            for (int i = 0; i < 8; i++)
#pragma unroll
                for (int j = 0; j < 4; j++) ffma2(acc[i][j], ad[i], bp[j]);
        }
        __syncthreads();
    }

    // epilogue: unpack, add bias, optional relu, store
    const int nb = n0 + (tx << 3);
    float bsv[8];
#pragma unroll
    for (int j = 0; j < 8; j++) bsv[j] = bias[nb + j];
#pragma unroll
    for (int i = 0; i < 8; i++) {
        float o[8];
#pragma unroll
        for (int j = 0; j < 4; j++) upk2(acc[i][j], o[2 * j], o[2 * j + 1]);
#pragma unroll
        for (int j = 0; j < 8; j++) {
            o[j] += bsv[j];
            if (relu) o[j] = fmaxf(o[j], 0.0f);
        }
        float* cp = C + (size_t)(m0 + (ty << 3) + i) * N + nb;
        *(float4*)(cp + 0) = make_float4(o[0], o[1], o[2], o[3]);
        *(float4*)(cp + 4) = make_float4(o[4], o[5], o[6], o[7]);
    }
}

// ---------------------------------------------------------------------------
// Attention: one CTA per batch. q,k in smem; scores 8x8 per head; softmax;
// ctx = attn @ v (v streamed via L1). Layout col = head*64 + d.
// ---------------------------------------------------------------------------
__global__ __launch_bounds__(256)
void attn_kernel(const float* __restrict__ q, const float* __restrict__ k,
                 const float* __restrict__ v, float* __restrict__ ctx) {
    __shared__ float qs[8][512];
    __shared__ float ks[8][512];
    __shared__ float sc[8][8][8];   // [head][i][j], softmaxed in place

    const int b   = blockIdx.x;
    const int tid = threadIdx.x;
    const size_t base = (size_t)b * (SEQ * DM);

    const float4* q4 = (const float4*)(q + base);
    const float4* k4 = (const float4*)(k + base);
#pragma unroll
    for (int t = tid; t < (SEQ * DM) / 4; t += 256) {
        ((float4*)qs)[t] = q4[t];
        ((float4*)ks)[t] = k4[t];
    }
    __syncthreads();

    // scores: 8 heads * 64 (i,j) pairs = 512 tasks
    for (int t = tid; t < 512; t += 256) {
        int h = t >> 6, r = t & 63, i = r >> 3, j = r & 7;
        const float* qp = &qs[i][h * DK];
        const float* kp = &ks[j][h * DK];
        float s = 0.0f;
#pragma unroll
        for (int d = 0; d < DK; d++) s = fmaf(qp[d], kp[d], s);
        sc[h][i][j] = s * 0.125f;     // 1/sqrt(64)
    }
    __syncthreads();

    // softmax over j per (head, i)
    if (tid < 64) {
        int h = tid >> 3, i = tid & 7;
        float* row = sc[h][i];
        float m = row[0];
#pragma unroll
        for (int j = 1; j < 8; j++) m = fmaxf(m, row[j]);
        float e[8], s = 0.0f;
#pragma unroll
        for (int j = 0; j < 8; j++) { e[j] = expf(row[j] - m); s += e[j]; }
        float inv = 1.0f / s;
#pragma unroll
        for (int j = 0; j < 8; j++) row[j] = e[j] * inv;
    }
    __syncthreads();

    // ctx[i, c] = sum_j attn[h,i,j] * v[j, c]   (c = h*64+d)
    for (int t = tid; t < SEQ * DM; t += 256) {
        int i = t >> 9, c = t & 511, h = c >> 6;
        const float* vp = v + base + c;
        const float* ar = sc[h][i];
        float s = 0.0f;
#pragma unroll
        for (int j = 0; j < 8; j++) s = fmaf(ar[j], vp[(size_t)j * DM], s);
        ctx[base + (size_t)i * DM + c] = s;
    }
}

// ---------------------------------------------------------------------------
// Residual + LayerNorm, in place on h: h = LN(t + h) * g + b
// One CTA (128 threads) per row of 512.
// ---------------------------------------------------------------------------
__global__ __launch_bounds__(128)
void ln_kernel(const float* __restrict__ t, float* __restrict__ h,
               const float* __restrict__ g, const float* __restrict__ b) {
    const int row = blockIdx.x, tid = threadIdx.x;
    const size_t base = (size_t)row * DM;

    float4 a = ((const float4*)(t + base))[tid];
    float4 r = ((const float4*)(h + base))[tid];
    float x0 = a.x + r.x, x1 = a.y + r.y, x2 = a.z + r.z, x3 = a.w + r.w;

    float s = x0 + x1 + x2 + x3;
#pragma unroll
    for (int o = 16; o; o >>= 1) s += __shfl_xor_sync(0xFFFFFFFFu, s, o);

    __shared__ float sm1[4], sm2[4];
    const int w = tid >> 5, lane = tid & 31;
    if (!lane) sm1[w] = s;
    __syncthreads();
    float mu = (sm1[0] + sm1[1] + sm1[2] + sm1[3]) * (1.0f / 512.0f);

    float d0 = x0 - mu, d1 = x1 - mu, d2 = x2 - mu, d3 = x3 - mu;
    float ss = d0 * d0 + d1 * d1 + d2 * d2 + d3 * d3;
#pragma unroll
    for (int o = 16; o; o >>= 1) ss += __shfl_xor_sync(0xFFFFFFFFu, ss, o);
    if (!lane) sm2[w] = ss;
    __syncthreads();
    float var = (sm2[0] + sm2[1] + sm2[2] + sm2[3]) * (1.0f / 512.0f);
    float inv = rsqrtf(var + LN_EPS);

    float4 gg = ((const float4*)g)[tid];
    float4 bb = ((const float4*)b)[tid];
    float4 o4;
    o4.x = d0 * inv * gg.x + bb.x;
    o4.y = d1 * inv * gg.y + bb.y;
    o4.z = d2 * inv * gg.z + bb.z;
    o4.w = d3 * inv * gg.w + bb.w;
    ((float4*)(h + base))[tid] = o4;
}

// ---------------------------------------------------------------------------
// Final gather: out[i, :] = h[i*8 + (i%8), :]
// ---------------------------------------------------------------------------
__global__ void gather_kernel(const float* __restrict__ h, float* __restrict__ out) {
    int t = blockIdx.x * 256 + threadIdx.x;            // < BATCH*DM
    int i = t >> 9, c = t & 511;
    out[t] = h[((size_t)i * 8 + (i & 7)) * DM + c];
}

// ---------------------------------------------------------------------------
// Launch
// ---------------------------------------------------------------------------
extern "C" void kernel_launch(void* const* d_in, const int* in_sizes, int n_in,
                              void* d_out, int out_size) {
    const float* x     = (const float*)d_in[0];
    const float* Wq    = (const float*)d_in[1];
    const float* bq    = (const float*)d_in[2];
    const float* Wk    = (const float*)d_in[3];
    const float* bk    = (const float*)d_in[4];
    const float* Wv    = (const float*)d_in[5];
    const float* bv    = (const float*)d_in[6];
    const float* Wo    = (const float*)d_in[7];
    const float* bo    = (const float*)d_in[8];
    const float* ln1g  = (const float*)d_in[9];
    const float* ln1b  = (const float*)d_in[10];
    const float* W1    = (const float*)d_in[11];
    const float* b1    = (const float*)d_in[12];
    const float* W2    = (const float*)d_in[13];
    const float* b2    = (const float*)d_in[14];
    const float* ln2g  = (const float*)d_in[15];
    const float* ln2b  = (const float*)d_in[16];
    float* out = (float*)d_out;

    float *h, *q, *k, *v, *t, *mid;
    cudaGetSymbolAddress((void**)&h,   g_h);
    cudaGetSymbolAddress((void**)&q,   g_q);
    cudaGetSymbolAddress((void**)&k,   g_k);
    cudaGetSymbolAddress((void**)&v,   g_v);
    cudaGetSymbolAddress((void**)&t,   g_t);
    cudaGetSymbolAddress((void**)&mid, g_mid);

    // h = x + positional encoding
    pos_kernel<<<(MTOK * DM) / 256, 256>>>(x, h);

    const dim3 gDM (DM / 128, MTOK / 128);    // (4, 1024)
    const dim3 gDH (DH / 128, MTOK / 128);    // (16, 1024)

    for (int l = 0; l < 2; l++) {
        const size_t oW  = (size_t)l * DM * DM;
        const size_t oV  = (size_t)l * DM;
        const size_t oW1 = (size_t)l * DM * DH;
        const size_t oB1 = (size_t)l * DH;
        const size_t oW2 = (size_t)l * DH * DM;

        // QKV projections
        gemm_kernel<<<gDM, 256>>>(h, Wq + oW, bq + oV, q, DM, DM, 0);
        gemm_kernel<<<gDM, 256>>>(h, Wk + oW, bk + oV, k, DM, DM, 0);
        gemm_kernel<<<gDM, 256>>>(h, Wv + oW, bv + oV, v, DM, DM, 0);

        // attention -> ctx in t
        attn_kernel<<<BATCH, 256>>>(q, k, v, t);

        // output projection (bias folded), then residual + LN1 into h
        gemm_kernel<<<gDM, 256>>>(t, Wo + oW, bo + oV, q, DM, DM, 0);
        ln_kernel<<<MTOK, 128>>>(q, h, ln1g + oV, ln1b + oV);

        // FFN: relu(h @ W1 + b1) @ W2 + b2, residual + LN2 into h
        gemm_kernel<<<gDH, 256>>>(h, W1 + oW1, b1 + oB1, mid, DH, DM, 1);
        gemm_kernel<<<gDM, 256>>>(mid, W2 + oW2, b2 + oV, t, DM, DH, 0);
        ln_kernel<<<MTOK, 128>>>(t, h, ln2g + oV, ln2b + oV);
    }

    // out[i] = h[i, i % 8]
    gather_kernel<<<(BATCH * DM) / 256, 256>>>(h, out);
}

// round 6
// speedup vs baseline: 2.8344x; 2.8344x over previous
#include <cuda_runtime.h>
#include <cuda_bf16.h>
#include <mma.h>
#include <cstdint>
#include <math.h>

using namespace nvcuda;

// ---------------------------------------------------------------------------
// Problem constants
// ---------------------------------------------------------------------------
#define BATCH   16384
#define SEQ     8
#define MTOK    (BATCH * SEQ)     // 131072 token rows
#define DM      512
#define DH      2048
#define DQKV    1536              // fused q|k|v width
#define LN_EPS  1e-6f

// GEMM tiling
#define BM      128
#define BN      128
#define BK      32
#define SSTRIDE 40                               // smem row stride in bf16 elems (80B)
#define PLANE_BYTES (128 * SSTRIDE * 2)          // 10240
#define STAGE_BYTES (4u * PLANE_BYTES)           // 40960: Ahi|Alo|Bhi|Blo
#define CSTRIDE 136                              // epilogue fp32 stride (544B)
#define GSMEM   (2u * STAGE_BYTES)               // 81920 (epilogue needs 69632)

// ---------------------------------------------------------------------------
// Scratch: bf16 hi/lo planes for all activations (device globals = legal scratch)
// ---------------------------------------------------------------------------
__device__ __nv_bfloat16 g_h_hi  [(size_t)MTOK * DM];
__device__ __nv_bfloat16 g_h_lo  [(size_t)MTOK * DM];
__device__ __nv_bfloat16 g_qkv_hi[(size_t)MTOK * DQKV];
__device__ __nv_bfloat16 g_qkv_lo[(size_t)MTOK * DQKV];
__device__ __nv_bfloat16 g_ctx_hi[(size_t)MTOK * DM];
__device__ __nv_bfloat16 g_ctx_lo[(size_t)MTOK * DM];
__device__ __nv_bfloat16 g_t_hi  [(size_t)MTOK * DM];
__device__ __nv_bfloat16 g_t_lo  [(size_t)MTOK * DM];
__device__ __nv_bfloat16 g_mid_hi[(size_t)MTOK * DH];
__device__ __nv_bfloat16 g_mid_lo[(size_t)MTOK * DH];
__device__ __nv_bfloat16 g_wqkvT_hi[(size_t)DQKV * DM];
__device__ __nv_bfloat16 g_wqkvT_lo[(size_t)DQKV * DM];
__device__ __nv_bfloat16 g_woT_hi  [(size_t)DM * DM];
__device__ __nv_bfloat16 g_woT_lo  [(size_t)DM * DM];
__device__ __nv_bfloat16 g_w1T_hi  [(size_t)DH * DM];
__device__ __nv_bfloat16 g_w1T_lo  [(size_t)DH * DM];
__device__ __nv_bfloat16 g_w2T_hi  [(size_t)DM * DH];
__device__ __nv_bfloat16 g_w2T_lo  [(size_t)DM * DH];
__device__ float         g_bqkv   [DQKV];

// ---------------------------------------------------------------------------
// Helpers
// ---------------------------------------------------------------------------
__device__ __forceinline__ uint32_t smem_u32(const void* p) {
    uint32_t a;
    asm("{ .reg .u64 t; cvta.to.shared.u64 t, %1; cvt.u32.u64 %0, t; }" : "=r"(a) : "l"(p));
    return a;
}
__device__ __forceinline__ void cp16(uint32_t sm, const void* g) {
    asm volatile("cp.async.cg.shared.global [%0], [%1], 16;" :: "r"(sm), "l"(g));
}
__device__ __forceinline__ void split2(float x, __nv_bfloat16& hi, __nv_bfloat16& lo) {
    hi = __float2bfloat16(x);
    lo = __float2bfloat16(x - __bfloat162float(hi));
}
__device__ __forceinline__ float join2(__nv_bfloat16 hi, __nv_bfloat16 lo) {
    return __bfloat162float(hi) + __bfloat162float(lo);
}
__device__ __forceinline__ float joinu(uint32_t h, uint32_t l) {
    return __bfloat162float(__ushort_as_bfloat16((unsigned short)h)) +
           __bfloat162float(__ushort_as_bfloat16((unsigned short)l));
}
__device__ __forceinline__ unsigned packbf(__nv_bfloat16 a, __nv_bfloat16 b) {
    return (unsigned)__bfloat16_as_ushort(a) | ((unsigned)__bfloat16_as_ushort(b) << 16);
}

// ---------------------------------------------------------------------------
// wmma tensor-core GEMM: C[M,N] = A @ B^T + bias (+relu), hi/lo split planes.
// A planes [M][K], B planes [N][K] (K-major). 3-product compensation.
// ---------------------------------------------------------------------------
__global__ __launch_bounds__(256)
void gemm_wmma(const __nv_bfloat16* __restrict__ Ahi, const __nv_bfloat16* __restrict__ Alo,
               const __nv_bfloat16* __restrict__ Bhi, const __nv_bfloat16* __restrict__ Blo,
               const float* __restrict__ bias,
               __nv_bfloat16* __restrict__ Chi, __nv_bfloat16* __restrict__ Clo,
               int N, int K, int relu)
{
    extern __shared__ char smem[];
    const uint32_t sb = smem_u32(smem);
    const int tid = threadIdx.x;
    const int wid = tid >> 5;
    const int wy  = wid & 3;          // 4 warps along M
    const int wx  = wid >> 2;         // 2 warps along N
    const int m0  = blockIdx.y << 7;
    const int n0  = blockIdx.x << 7;
    const int NC  = K / BK;

    wmma::fragment<wmma::accumulator, 16, 16, 16, float> acc[2][4];
#pragma unroll
    for (int m = 0; m < 2; m++)
#pragma unroll
        for (int n = 0; n < 4; n++) wmma::fill_fragment(acc[m][n], 0.0f);

    // stage loader: 4 planes x 128 rows x 64B (as 4x16B chunks) = 2048 cp16
    auto load_stage = [&](int st, int k0) {
        const uint32_t base = sb + (uint32_t)st * STAGE_BYTES;
        for (int i = tid; i < 2048; i += 256) {
            const int plane = i >> 9;             // 0:Ahi 1:Alo 2:Bhi 3:Blo
            const int r     = (i >> 2) & 127;
            const int c     = (i & 3) << 4;       // byte offset in 64B row chunk
            const uint32_t saddr = base + (uint32_t)plane * PLANE_BYTES
                                 + (uint32_t)r * (SSTRIDE * 2) + c;
            const __nv_bfloat16* gp;
            if      (plane == 0) gp = Ahi + (size_t)(m0 + r) * K + k0;
            else if (plane == 1) gp = Alo + (size_t)(m0 + r) * K + k0;
            else if (plane == 2) gp = Bhi + (size_t)(n0 + r) * K + k0;
            else                 gp = Blo + (size_t)(n0 + r) * K + k0;
            cp16(saddr, (const char*)gp + c);
        }
        asm volatile("cp.async.commit_group;" ::: "memory");
    };

    load_stage(0, 0);

    for (int ch = 0; ch < NC; ch++) {
        if (ch + 1 < NC) {
            load_stage((ch + 1) & 1, (ch + 1) * BK);
            asm volatile("cp.async.wait_group 1;" ::: "memory");
        } else {
            asm volatile("cp.async.wait_group 0;" ::: "memory");
        }
        __syncthreads();

        const __nv_bfloat16* ss =
            (const __nv_bfloat16*)(smem + (size_t)(ch & 1) * STAGE_BYTES);
        const __nv_bfloat16* sAhi = ss;
        const __nv_bfloat16* sAlo = ss + 128 * SSTRIDE;
        const __nv_bfloat16* sBhi = ss + 2 * 128 * SSTRIDE;
        const __nv_bfloat16* sBlo = ss + 3 * 128 * SSTRIDE;

#pragma unroll
        for (int ks = 0; ks < 2; ks++) {
            wmma::fragment<wmma::matrix_a, 16, 16, 16, __nv_bfloat16, wmma::row_major> ah[2], al[2];
#pragma unroll
            for (int m = 0; m < 2; m++) {
                const int row = wy * 32 + m * 16;
                wmma::load_matrix_sync(ah[m], sAhi + row * SSTRIDE + ks * 16, SSTRIDE);
                wmma::load_matrix_sync(al[m], sAlo + row * SSTRIDE + ks * 16, SSTRIDE);
            }
#pragma unroll
            for (int n = 0; n < 4; n++) {
                const int col = wx * 64 + n * 16;
                wmma::fragment<wmma::matrix_b, 16, 16, 16, __nv_bfloat16, wmma::col_major> bh, bl;
                wmma::load_matrix_sync(bh, sBhi + col * SSTRIDE + ks * 16, SSTRIDE);
                wmma::load_matrix_sync(bl, sBlo + col * SSTRIDE + ks * 16, SSTRIDE);
#pragma unroll
                for (int m = 0; m < 2; m++) {
                    wmma::mma_sync(acc[m][n], ah[m], bh, acc[m][n]);
                    wmma::mma_sync(acc[m][n], ah[m], bl, acc[m][n]);
                    wmma::mma_sync(acc[m][n], al[m], bh, acc[m][n]);
                }
            }
        }
        __syncthreads();
    }

    // ---- epilogue: stage acc -> smem fp32, then bias/relu/split -> gmem ----
    float* cs = (float*)smem;
#pragma unroll
    for (int m = 0; m < 2; m++)
#pragma unroll
        for (int n = 0; n < 4; n++)
            wmma::store_matrix_sync(cs + (size_t)(wy * 32 + m * 16) * CSTRIDE
                                       + wx * 64 + n * 16,
                                    acc[m][n], CSTRIDE, wmma::mem_row_major);
    __syncthreads();

    {
        const int r    = tid >> 1;             // 0..127
        const int half = tid & 1;              // 0..1 (64 cols each)
        const int row  = m0 + r;
        const int cb   = half * 64;
        const float* src = cs + (size_t)r * CSTRIDE + cb;
        __nv_bfloat16* dh = Chi + (size_t)row * N + n0 + cb;
        __nv_bfloat16* dl = Clo + (size_t)row * N + n0 + cb;
        const float* bp = bias + n0 + cb;
#pragma unroll
        for (int g = 0; g < 8; g++) {
            unsigned hw[4], lw[4];
#pragma unroll
            for (int j = 0; j < 4; j++) {
                float v0 = src[g * 8 + 2 * j]     + bp[g * 8 + 2 * j];
                float v1 = src[g * 8 + 2 * j + 1] + bp[g * 8 + 2 * j + 1];
                if (relu) { v0 = fmaxf(v0, 0.0f); v1 = fmaxf(v1, 0.0f); }
                __nv_bfloat16 h0, l0, h1, l1;
                split2(v0, h0, l0);
                split2(v1, h1, l1);
                hw[j] = packbf(h0, h1);
                lw[j] = packbf(l0, l1);
            }
            *(uint4*)(dh + g * 8) = *(const uint4*)hw;
            *(uint4*)(dl + g * 8) = *(const uint4*)lw;
        }
    }
}

// ---------------------------------------------------------------------------
// Weight split-transpose: W[K][N] fp32 -> T[rowOff+n][k] hi/lo bf16 (row stride K)
// ---------------------------------------------------------------------------
__global__ __launch_bounds__(256)
void wsplit_kernel(const float* __restrict__ W, int K, int N,
                   __nv_bfloat16* __restrict__ Thi, __nv_bfloat16* __restrict__ Tlo,
                   int rowOff)
{
    __shared__ float tile[32][33];
    const int tx = threadIdx.x & 31, ty = threadIdx.x >> 5;
    const int n0 = blockIdx.x << 5, k0 = blockIdx.y << 5;
#pragma unroll
    for (int r = 0; r < 4; r++) {
        int k = k0 + ty + r * 8;
        tile[ty + r * 8][tx] = W[(size_t)k * N + n0 + tx];
    }
    __syncthreads();
#pragma unroll
    for (int r = 0; r < 4; r++) {
        int n = n0 + ty + r * 8;
        float v = tile[tx][ty + r * 8];
        __nv_bfloat16 hi, lo;
        split2(v, hi, lo);
        size_t o = (size_t)(rowOff + n) * K + k0 + tx;
        Thi[o] = hi; Tlo[o] = lo;
    }
}

__global__ void bcat_kernel(const float* __restrict__ a, const float* __restrict__ b,
                            const float* __restrict__ c, float* __restrict__ o) {
    int t = blockIdx.x * 256 + threadIdx.x;
    if (t < 512) o[t] = a[t];
    else if (t < 1024) o[t] = b[t - 512];
    else if (t < 1536) o[t] = c[t - 1024];
}

// ---------------------------------------------------------------------------
// Positional encoding: h = split(x + sinusoid)
// ---------------------------------------------------------------------------
__global__ void pos_kernel(const float* __restrict__ x,
                           __nv_bfloat16* __restrict__ hhi, __nv_bfloat16* __restrict__ hlo) {
    int t = blockIdx.x * 256 + threadIdx.x;
    int c = t & 511;
    int s = (t >> 9) & 7;
    int d2 = c >> 1;
    float e = (float)(2 * d2) * (1.0f / 512.0f);
    float ang = (float)s * powf(10000.0f, -e);
    float p = (c & 1) ? cosf(ang) : sinf(ang);
    __nv_bfloat16 hi, lo;
    split2(x[t] + p, hi, lo);
    hhi[t] = hi; hlo[t] = lo;
}

// ---------------------------------------------------------------------------
// Attention: qkv fused planes [M][1536] -> ctx planes [M][512]
// ---------------------------------------------------------------------------
__global__ __launch_bounds__(256)
void attn_kernel(const __nv_bfloat16* __restrict__ qh, const __nv_bfloat16* __restrict__ ql,
                 __nv_bfloat16* __restrict__ ch, __nv_bfloat16* __restrict__ cl) {
    __shared__ float qs[8][512];
    __shared__ float ks[8][512];
    __shared__ float sc[8][8][8];

    const int b = blockIdx.x, tid = threadIdx.x;
    const size_t rbase = (size_t)b * 8 * DQKV;

    for (int t = tid; t < 512; t += 256) {
        int i = t >> 6;
        int c8 = (t & 63) << 3;
        size_t qo = rbase + (size_t)i * DQKV + c8;
        uint4 h4 = *(const uint4*)(qh + qo);
        uint4 l4 = *(const uint4*)(ql + qo);
        const unsigned* hu = (const unsigned*)&h4;
        const unsigned* lu = (const unsigned*)&l4;
#pragma unroll
        for (int w = 0; w < 4; w++) {
            qs[i][c8 + 2 * w]     = joinu(hu[w] & 0xFFFFu, lu[w] & 0xFFFFu);
            qs[i][c8 + 2 * w + 1] = joinu(hu[w] >> 16,     lu[w] >> 16);
        }
        size_t ko = qo + 512;
        h4 = *(const uint4*)(qh + ko);
        l4 = *(const uint4*)(ql + ko);
#pragma unroll
        for (int w = 0; w < 4; w++) {
            ks[i][c8 + 2 * w]     = joinu(hu[w] & 0xFFFFu, lu[w] & 0xFFFFu);
            ks[i][c8 + 2 * w + 1] = joinu(hu[w] >> 16,     lu[w] >> 16);
        }
    }
    __syncthreads();

    for (int t = tid; t < 512; t += 256) {
        int h = t >> 6, r = t & 63, i = r >> 3, j = r & 7;
        const float* qp = &qs[i][h * 64];
        const float* kp = &ks[j][h * 64];
        float s = 0.0f;
#pragma unroll
        for (int d = 0; d < 64; d++) s = fmaf(qp[d], kp[d], s);
        sc[h][i][j] = s * 0.125f;
    }
    __syncthreads();

    if (tid < 64) {
        int h = tid >> 3, i = tid & 7;
        float* row = sc[h][i];
        float m = row[0];
#pragma unroll
        for (int j = 1; j < 8; j++) m = fmaxf(m, row[j]);
        float e[8], s = 0.0f;
#pragma unroll
        for (int j = 0; j < 8; j++) { e[j] = expf(row[j] - m); s += e[j]; }
        float inv = 1.0f / s;
#pragma unroll
        for (int j = 0; j < 8; j++) row[j] = e[j] * inv;
    }
    __syncthreads();

    const size_t obase = (size_t)b * 8 * DM;
    for (int t = tid; t < 4096; t += 256) {
        int i = t >> 9, c = t & 511, h = c >> 6;
        const __nv_bfloat16* vh = qh + rbase + 1024 + c;
        const __nv_bfloat16* vl = ql + rbase + 1024 + c;
        const float* ar = sc[h][i];
        float s = 0.0f;
#pragma unroll
        for (int j = 0; j < 8; j++) {
            float vv = join2(vh[(size_t)j * DQKV], vl[(size_t)j * DQKV]);
            s = fmaf(ar[j], vv, s);
        }
        __nv_bfloat16 hi, lo;
        split2(s, hi, lo);
        size_t o = obase + (size_t)i * DM + c;
        ch[o] = hi; cl[o] = lo;
    }
}

// ---------------------------------------------------------------------------
// Residual + LayerNorm: h = LN(t + h) * g + b  (hi/lo planes)
// ---------------------------------------------------------------------------
__global__ __launch_bounds__(128)
void ln_kernel(const __nv_bfloat16* __restrict__ th, const __nv_bfloat16* __restrict__ tl,
               __nv_bfloat16* __restrict__ hh, __nv_bfloat16* __restrict__ hl,
               const float* __restrict__ g, const float* __restrict__ bb) {
    const int row = blockIdx.x, tid = threadIdx.x;
    const size_t base = (size_t)row * DM + tid * 4;

    uint2 t_h = *(const uint2*)(th + base);
    uint2 t_l = *(const uint2*)(tl + base);
    uint2 h_h = *(const uint2*)(hh + base);
    uint2 h_l = *(const uint2*)(hl + base);
    const unsigned* thu = (const unsigned*)&t_h;
    const unsigned* tlu = (const unsigned*)&t_l;
    const unsigned* hhu = (const unsigned*)&h_h;
    const unsigned* hlu = (const unsigned*)&h_l;

    float x[4];
#pragma unroll
    for (int w = 0; w < 2; w++) {
        x[2 * w]     = joinu(thu[w] & 0xFFFFu, tlu[w] & 0xFFFFu) +
                       joinu(hhu[w] & 0xFFFFu, hlu[w] & 0xFFFFu);
        x[2 * w + 1] = joinu(thu[w] >> 16, tlu[w] >> 16) +
                       joinu(hhu[w] >> 16, hlu[w] >> 16);
    }

    float s = x[0] + x[1] + x[2] + x[3];
#pragma unroll
    for (int o = 16; o; o >>= 1) s += __shfl_xor_sync(0xFFFFFFFFu, s, o);

    __shared__ float sm1[4], sm2[4];
    const int w = tid >> 5, lane = tid & 31;
    if (!lane) sm1[w] = s;
    __syncthreads();
    float mu = (sm1[0] + sm1[1] + sm1[2] + sm1[3]) * (1.0f / 512.0f);

    float d0 = x[0] - mu, d1 = x[1] - mu, d2 = x[2] - mu, d3 = x[3] - mu;
    float ss = d0 * d0 + d1 * d1 + d2 * d2 + d3 * d3;
#pragma unroll
    for (int o = 16; o; o >>= 1) ss += __shfl_xor_sync(0xFFFFFFFFu, ss, o);
    if (!lane) sm2[w] = ss;
    __syncthreads();
    float var = (sm2[0] + sm2[1] + sm2[2] + sm2[3]) * (1.0f / 512.0f);
    float inv = rsqrtf(var + LN_EPS);

    float4 gg = ((const float4*)g)[tid];
    float4 bv = ((const float4*)bb)[tid];
    float o0 = d0 * inv * gg.x + bv.x;
    float o1 = d1 * inv * gg.y + bv.y;
    float o2 = d2 * inv * gg.z + bv.z;
    float o3 = d3 * inv * gg.w + bv.w;

    __nv_bfloat16 a0, b0, a1, b1, a2, b2, a3, b3;
    split2(o0, a0, b0); split2(o1, a1, b1);
    split2(o2, a2, b2); split2(o3, a3, b3);
    uint2 oh = make_uint2(packbf(a0, a1), packbf(a2, a3));
    uint2 ol = make_uint2(packbf(b0, b1), packbf(b2, b3));
    *(uint2*)(hh + base) = oh;
    *(uint2*)(hl + base) = ol;
}

// ---------------------------------------------------------------------------
// Final gather: out[i,:] = h[i*8 + i%8, :]
// ---------------------------------------------------------------------------
__global__ void gather_kernel(const __nv_bfloat16* __restrict__ hh,
                              const __nv_bfloat16* __restrict__ hl,
                              float* __restrict__ out) {
    int t = blockIdx.x * 256 + threadIdx.x;
    int i = t >> 9, c = t & 511;
    size_t src = ((size_t)i * 8 + (i & 7)) * DM + c;
    out[t] = join2(hh[src], hl[src]);
}

// ---------------------------------------------------------------------------
// Launch
// ---------------------------------------------------------------------------
extern "C" void kernel_launch(void* const* d_in, const int* in_sizes, int n_in,
                              void* d_out, int out_size) {
    const float* x    = (const float*)d_in[0];
    const float* Wq   = (const float*)d_in[1];
    const float* bq   = (const float*)d_in[2];
    const float* Wk   = (const float*)d_in[3];
    const float* bk   = (const float*)d_in[4];
    const float* Wv   = (const float*)d_in[5];
    const float* bv   = (const float*)d_in[6];
    const float* Wo   = (const float*)d_in[7];
    const float* bo   = (const float*)d_in[8];
    const float* ln1g = (const float*)d_in[9];
    const float* ln1b = (const float*)d_in[10];
    const float* W1   = (const float*)d_in[11];
    const float* b1   = (const float*)d_in[12];
    const float* W2   = (const float*)d_in[13];
    const float* b2   = (const float*)d_in[14];
    const float* ln2g = (const float*)d_in[15];
    const float* ln2b = (const float*)d_in[16];
    float* out = (float*)d_out;

    __nv_bfloat16 *h_hi, *h_lo, *qkv_hi, *qkv_lo, *ctx_hi, *ctx_lo,
                  *t_hi, *t_lo, *mid_hi, *mid_lo,
                  *wqkvT_hi, *wqkvT_lo, *woT_hi, *woT_lo,
                  *w1T_hi, *w1T_lo, *w2T_hi, *w2T_lo;
    float* bqkv;
    cudaGetSymbolAddress((void**)&h_hi, g_h_hi);     cudaGetSymbolAddress((void**)&h_lo, g_h_lo);
    cudaGetSymbolAddress((void**)&qkv_hi, g_qkv_hi); cudaGetSymbolAddress((void**)&qkv_lo, g_qkv_lo);
    cudaGetSymbolAddress((void**)&ctx_hi, g_ctx_hi); cudaGetSymbolAddress((void**)&ctx_lo, g_ctx_lo);
    cudaGetSymbolAddress((void**)&t_hi, g_t_hi);     cudaGetSymbolAddress((void**)&t_lo, g_t_lo);
    cudaGetSymbolAddress((void**)&mid_hi, g_mid_hi); cudaGetSymbolAddress((void**)&mid_lo, g_mid_lo);
    cudaGetSymbolAddress((void**)&wqkvT_hi, g_wqkvT_hi); cudaGetSymbolAddress((void**)&wqkvT_lo, g_wqkvT_lo);
    cudaGetSymbolAddress((void**)&woT_hi, g_woT_hi); cudaGetSymbolAddress((void**)&woT_lo, g_woT_lo);
    cudaGetSymbolAddress((void**)&w1T_hi, g_w1T_hi); cudaGetSymbolAddress((void**)&w1T_lo, g_w1T_lo);
    cudaGetSymbolAddress((void**)&w2T_hi, g_w2T_hi); cudaGetSymbolAddress((void**)&w2T_lo, g_w2T_lo);
    cudaGetSymbolAddress((void**)&bqkv, g_bqkv);

    cudaFuncSetAttribute(gemm_wmma, cudaFuncAttributeMaxDynamicSharedMemorySize, GSMEM);

    // h = split(x + pos)
    pos_kernel<<<(MTOK * DM) / 256, 256>>>(x, h_hi, h_lo);

    for (int l = 0; l < 2; l++) {
        const size_t oW  = (size_t)l * DM * DM;
        const size_t oV  = (size_t)l * DM;
        const size_t oW1 = (size_t)l * DM * DH;
        const size_t oB1 = (size_t)l * DH;
        const size_t oW2 = (size_t)l * DH * DM;

        // weight prep: split + transpose into [N][K] K-major planes
        wsplit_kernel<<<dim3(16, 16), 256>>>(Wq + oW, DM, DM, wqkvT_hi, wqkvT_lo, 0);
        wsplit_kernel<<<dim3(16, 16), 256>>>(Wk + oW, DM, DM, wqkvT_hi, wqkvT_lo, 512);
        wsplit_kernel<<<dim3(16, 16), 256>>>(Wv + oW, DM, DM, wqkvT_hi, wqkvT_lo, 1024);
        bcat_kernel<<<6, 256>>>(bq + oV, bk + oV, bv + oV, bqkv);
        wsplit_kernel<<<dim3(16, 16), 256>>>(Wo + oW, DM, DM, woT_hi, woT_lo, 0);
        wsplit_kernel<<<dim3(64, 16), 256>>>(W1 + oW1, DM, DH, w1T_hi, w1T_lo, 0);
        wsplit_kernel<<<dim3(16, 64), 256>>>(W2 + oW2, DH, DM, w2T_hi, w2T_lo, 0);

        // fused QKV projection: [M,512] @ [512,1536]
        gemm_wmma<<<dim3(DQKV / BN, MTOK / BM), 256, GSMEM>>>(
            h_hi, h_lo, wqkvT_hi, wqkvT_lo, bqkv, qkv_hi, qkv_lo, DQKV, DM, 0);

        attn_kernel<<<BATCH, 256>>>(qkv_hi, qkv_lo, ctx_hi, ctx_lo);

        // output projection, residual + LN1
        gemm_wmma<<<dim3(DM / BN, MTOK / BM), 256, GSMEM>>>(
            ctx_hi, ctx_lo, woT_hi, woT_lo, bo + oV, t_hi, t_lo, DM, DM, 0);
        ln_kernel<<<MTOK, 128>>>(t_hi, t_lo, h_hi, h_lo, ln1g + oV, ln1b + oV);

        // FFN
        gemm_wmma<<<dim3(DH / BN, MTOK / BM), 256, GSMEM>>>(
            h_hi, h_lo, w1T_hi, w1T_lo, b1 + oB1, mid_hi, mid_lo, DH, DM, 1);
        gemm_wmma<<<dim3(DM / BN, MTOK / BM), 256, GSMEM>>>(
            mid_hi, mid_lo, w2T_hi, w2T_lo, b2 + oV, t_hi, t_lo, DM, DH, 0);
        ln_kernel<<<MTOK, 128>>>(t_hi, t_lo, h_hi, h_lo, ln2g + oV, ln2b + oV);
    }

    gather_kernel<<<(BATCH * DM) / 256, 256>>>(h_hi, h_lo, out);
}

// round 9
// speedup vs baseline: 4.3701x; 1.5418x over previous
#include <cuda_runtime.h>
#include <cuda_bf16.h>
#include <mma.h>
#include <cstdint>
#include <math.h>

using namespace nvcuda;

// ---------------------------------------------------------------------------
// Problem constants
// ---------------------------------------------------------------------------
#define BATCH   16384
#define SEQ     8
#define MTOK    (BATCH * SEQ)     // 131072 token rows
#define MSEL    BATCH             // 16384 selected rows (layer 2 compact path)
#define DM      512
#define DH      2048
#define DQKV    1536              // fused q|k|v width (layer 1)
#define LN_EPS  1e-6f

// GEMM tiling
#define BM      128
#define BN      128
#define BK      32
#define SSTRIDE 40                               // smem row stride in bf16 elems (80B)
#define PLANE_BYTES (128 * SSTRIDE * 2)          // 10240
#define STAGE_BYTES (4u * PLANE_BYTES)           // 40960: Ahi|Alo|Bhi|Blo
#define CSTRIDE 136                              // epilogue fp32 stride (544B)
#define GSMEM   (2u * STAGE_BYTES)               // 81920 (epilogue needs 69632)

// ---------------------------------------------------------------------------
// Scratch (device globals = legal scratch)
// ---------------------------------------------------------------------------
__device__ __nv_bfloat16 g_h_hi  [(size_t)MTOK * DM];
__device__ __nv_bfloat16 g_h_lo  [(size_t)MTOK * DM];
__device__ __nv_bfloat16 g_qkv_hi[(size_t)MTOK * DQKV];   // L1: qkv. L2: kv [M][1024]
__device__ __nv_bfloat16 g_qkv_lo[(size_t)MTOK * DQKV];
__device__ __nv_bfloat16 g_ctx_hi[(size_t)MTOK * DM];
__device__ __nv_bfloat16 g_ctx_lo[(size_t)MTOK * DM];
__device__ __nv_bfloat16 g_t_hi  [(size_t)MTOK * DM];
__device__ __nv_bfloat16 g_t_lo  [(size_t)MTOK * DM];
__device__ __nv_bfloat16 g_mid_hi[(size_t)MTOK * DH];
__device__ __nv_bfloat16 g_mid_lo[(size_t)MTOK * DH];
// layer-2 compact buffers
__device__ __nv_bfloat16 g_sh_hi [(size_t)MSEL * DM];     // selected h rows
__device__ __nv_bfloat16 g_sh_lo [(size_t)MSEL * DM];
__device__ __nv_bfloat16 g_qs_hi [(size_t)MSEL * DM];     // selected q
__device__ __nv_bfloat16 g_qs_lo [(size_t)MSEL * DM];
// split-transposed weights for the current layer
__device__ __nv_bfloat16 g_wqkvT_hi[(size_t)DQKV * DM];
__device__ __nv_bfloat16 g_wqkvT_lo[(size_t)DQKV * DM];
__device__ __nv_bfloat16 g_woT_hi  [(size_t)DM * DM];
__device__ __nv_bfloat16 g_woT_lo  [(size_t)DM * DM];
__device__ __nv_bfloat16 g_w1T_hi  [(size_t)DH * DM];
__device__ __nv_bfloat16 g_w1T_lo  [(size_t)DH * DM];
__device__ __nv_bfloat16 g_w2T_hi  [(size_t)DM * DH];
__device__ __nv_bfloat16 g_w2T_lo  [(size_t)DM * DH];
__device__ float         g_bqkv   [DQKV];

// ---------------------------------------------------------------------------
// Helpers
// ---------------------------------------------------------------------------
__device__ __forceinline__ uint32_t smem_u32(const void* p) {
    uint32_t a;
    asm("{ .reg .u64 t; cvta.to.shared.u64 t, %1; cvt.u32.u64 %0, t; }" : "=r"(a) : "l"(p));
    return a;
}
__device__ __forceinline__ void cp16(uint32_t sm, const void* g) {
    asm volatile("cp.async.cg.shared.global [%0], [%1], 16;" :: "r"(sm), "l"(g));
}
__device__ __forceinline__ void split2(float x, __nv_bfloat16& hi, __nv_bfloat16& lo) {
    hi = __float2bfloat16(x);
    lo = __float2bfloat16(x - __bfloat162float(hi));
}
__device__ __forceinline__ float join2(__nv_bfloat16 hi, __nv_bfloat16 lo) {
    return __bfloat162float(hi) + __bfloat162float(lo);
}
__device__ __forceinline__ float joinu(uint32_t h, uint32_t l) {
    return __bfloat162float(__ushort_as_bfloat16((unsigned short)h)) +
           __bfloat162float(__ushort_as_bfloat16((unsigned short)l));
}
__device__ __forceinline__ unsigned packbf(__nv_bfloat16 a, __nv_bfloat16 b) {
    return (unsigned)__bfloat16_as_ushort(a) | ((unsigned)__bfloat16_as_ushort(b) << 16);
}

// ---------------------------------------------------------------------------
// wmma tensor-core GEMM (proven in R6: 21.6ms total, rel_err 1.1e-5)
// ---------------------------------------------------------------------------
__global__ __launch_bounds__(256)
void gemm_wmma(const __nv_bfloat16* __restrict__ Ahi, const __nv_bfloat16* __restrict__ Alo,
               const __nv_bfloat16* __restrict__ Bhi, const __nv_bfloat16* __restrict__ Blo,
               const float* __restrict__ bias,
               __nv_bfloat16* __restrict__ Chi, __nv_bfloat16* __restrict__ Clo,
               int N, int K, int relu)
{
    extern __shared__ char smem[];
    const uint32_t sb = smem_u32(smem);
    const int tid = threadIdx.x;
    const int wid = tid >> 5;
    const int wy  = wid & 3;
    const int wx  = wid >> 2;
    const int m0  = blockIdx.y << 7;
    const int n0  = blockIdx.x << 7;
    const int NC  = K / BK;

    wmma::fragment<wmma::accumulator, 16, 16, 16, float> acc[2][4];
#pragma unroll
    for (int m = 0; m < 2; m++)
#pragma unroll
        for (int n = 0; n < 4; n++) wmma::fill_fragment(acc[m][n], 0.0f);

    auto load_stage = [&](int st, int k0) {
        const uint32_t base = sb + (uint32_t)st * STAGE_BYTES;
        for (int i = tid; i < 2048; i += 256) {
            const int plane = i >> 9;
            const int r     = (i >> 2) & 127;
            const int c     = (i & 3) << 4;
            const uint32_t saddr = base + (uint32_t)plane * PLANE_BYTES
                                 + (uint32_t)r * (SSTRIDE * 2) + c;
            const __nv_bfloat16* gp;
            if      (plane == 0) gp = Ahi + (size_t)(m0 + r) * K + k0;
            else if (plane == 1) gp = Alo + (size_t)(m0 + r) * K + k0;
            else if (plane == 2) gp = Bhi + (size_t)(n0 + r) * K + k0;
            else                 gp = Blo + (size_t)(n0 + r) * K + k0;
            cp16(saddr, (const char*)gp + c);
        }
        asm volatile("cp.async.commit_group;" ::: "memory");
    };

    load_stage(0, 0);

    for (int ch = 0; ch < NC; ch++) {
        if (ch + 1 < NC) {
            load_stage((ch + 1) & 1, (ch + 1) * BK);
            asm volatile("cp.async.wait_group 1;" ::: "memory");
        } else {
            asm volatile("cp.async.wait_group 0;" ::: "memory");
        }
        __syncthreads();

        const __nv_bfloat16* ss =
            (const __nv_bfloat16*)(smem + (size_t)(ch & 1) * STAGE_BYTES);
        const __nv_bfloat16* sAhi = ss;
        const __nv_bfloat16* sAlo = ss + 128 * SSTRIDE;
        const __nv_bfloat16* sBhi = ss + 2 * 128 * SSTRIDE;
        const __nv_bfloat16* sBlo = ss + 3 * 128 * SSTRIDE;

#pragma unroll
        for (int ks = 0; ks < 2; ks++) {
            wmma::fragment<wmma::matrix_a, 16, 16, 16, __nv_bfloat16, wmma::row_major> ah[2], al[2];
#pragma unroll
            for (int m = 0; m < 2; m++) {
                const int row = wy * 32 + m * 16;
                wmma::load_matrix_sync(ah[m], sAhi + row * SSTRIDE + ks * 16, SSTRIDE);
                wmma::load_matrix_sync(al[m], sAlo + row * SSTRIDE + ks * 16, SSTRIDE);
            }
#pragma unroll
            for (int n = 0; n < 4; n++) {
                const int col = wx * 64 + n * 16;
                wmma::fragment<wmma::matrix_b, 16, 16, 16, __nv_bfloat16, wmma::col_major> bh, bl;
                wmma::load_matrix_sync(bh, sBhi + col * SSTRIDE + ks * 16, SSTRIDE);
                wmma::load_matrix_sync(bl, sBlo + col * SSTRIDE + ks * 16, SSTRIDE);
#pragma unroll
                for (int m = 0; m < 2; m++) {
                    wmma::mma_sync(acc[m][n], ah[m], bh, acc[m][n]);
                    wmma::mma_sync(acc[m][n], ah[m], bl, acc[m][n]);
                    wmma::mma_sync(acc[m][n], al[m], bh, acc[m][n]);
                }
            }
        }
        __syncthreads();
    }

    float* cs = (float*)smem;
#pragma unroll
    for (int m = 0; m < 2; m++)
#pragma unroll
        for (int n = 0; n < 4; n++)
            wmma::store_matrix_sync(cs + (size_t)(wy * 32 + m * 16) * CSTRIDE
                                       + wx * 64 + n * 16,
                                    acc[m][n], CSTRIDE, wmma::mem_row_major);
    __syncthreads();

    {
        const int r    = tid >> 1;
        const int half = tid & 1;
        const int row  = m0 + r;
        const int cb   = half * 64;
        const float* src = cs + (size_t)r * CSTRIDE + cb;
        __nv_bfloat16* dh = Chi + (size_t)row * N + n0 + cb;
        __nv_bfloat16* dl = Clo + (size_t)row * N + n0 + cb;
        const float* bp = bias + n0 + cb;
#pragma unroll
        for (int g = 0; g < 8; g++) {
            unsigned hw[4], lw[4];
#pragma unroll
            for (int j = 0; j < 4; j++) {
                float v0 = src[g * 8 + 2 * j]     + bp[g * 8 + 2 * j];
                float v1 = src[g * 8 + 2 * j + 1] + bp[g * 8 + 2 * j + 1];
                if (relu) { v0 = fmaxf(v0, 0.0f); v1 = fmaxf(v1, 0.0f); }
                __nv_bfloat16 h0, l0, h1, l1;
                split2(v0, h0, l0);
                split2(v1, h1, l1);
                hw[j] = packbf(h0, h1);
                lw[j] = packbf(l0, l1);
            }
            *(uint4*)(dh + g * 8) = *(const uint4*)hw;
            *(uint4*)(dl + g * 8) = *(const uint4*)lw;
        }
    }
}

// ---------------------------------------------------------------------------
// Weight split-transpose: W[K][N] fp32 -> T[rowOff+n][k] hi/lo bf16
// ---------------------------------------------------------------------------
__global__ __launch_bounds__(256)
void wsplit_kernel(const float* __restrict__ W, int K, int N,
                   __nv_bfloat16* __restrict__ Thi, __nv_bfloat16* __restrict__ Tlo,
                   int rowOff)
{
    __shared__ float tile[32][33];
    const int tx = threadIdx.x & 31, ty = threadIdx.x >> 5;
    const int n0 = blockIdx.x << 5, k0 = blockIdx.y << 5;
#pragma unroll
    for (int r = 0; r < 4; r++) {
        int k = k0 + ty + r * 8;
        tile[ty + r * 8][tx] = W[(size_t)k * N + n0 + tx];
    }
    __syncthreads();
#pragma unroll
    for (int r = 0; r < 4; r++) {
        int n = n0 + ty + r * 8;
        float v = tile[tx][ty + r * 8];
        __nv_bfloat16 hi, lo;
        split2(v, hi, lo);
        size_t o = (size_t)(rowOff + n) * K + k0 + tx;
        Thi[o] = hi; Tlo[o] = lo;
    }
}

__global__ void bcat_kernel(const float* __restrict__ a, const float* __restrict__ b,
                            const float* __restrict__ c, float* __restrict__ o) {
    int t = blockIdx.x * 256 + threadIdx.x;
    if (t < 512) o[t] = a[t];
    else if (t < 1024) o[t] = b[t - 512];
    else if (t < 1536) o[t] = c[t - 1024];
}

// ---------------------------------------------------------------------------
// Positional encoding: h = split(x + sinusoid)
// ---------------------------------------------------------------------------
__global__ void pos_kernel(const float* __restrict__ x,
                           __nv_bfloat16* __restrict__ hhi, __nv_bfloat16* __restrict__ hlo) {
    int t = blockIdx.x * 256 + threadIdx.x;
    int c = t & 511;
    int s = (t >> 9) & 7;
    int d2 = c >> 1;
    float e = (float)(2 * d2) * (1.0f / 512.0f);
    float ang = (float)s * powf(10000.0f, -e);
    float p = (c & 1) ? cosf(ang) : sinf(ang);
    __nv_bfloat16 hi, lo;
    split2(x[t] + p, hi, lo);
    hhi[t] = hi; hlo[t] = lo;
}

// ---------------------------------------------------------------------------
// Layer-1 attention: qkv fused planes [M][1536] -> ctx planes [M][512]
// ---------------------------------------------------------------------------
__global__ __launch_bounds__(256)
void attn_kernel(const __nv_bfloat16* __restrict__ qh, const __nv_bfloat16* __restrict__ ql,
                 __nv_bfloat16* __restrict__ ch, __nv_bfloat16* __restrict__ cl) {
    __shared__ float qs[8][512];
    __shared__ float ks[8][512];
    __shared__ float sc[8][8][8];

    const int b = blockIdx.x, tid = threadIdx.x;
    const size_t rbase = (size_t)b * 8 * DQKV;

    for (int t = tid; t < 512; t += 256) {
        int i = t >> 6;
        int c8 = (t & 63) << 3;
        size_t qo = rbase + (size_t)i * DQKV + c8;
        uint4 h4 = *(const uint4*)(qh + qo);
        uint4 l4 = *(const uint4*)(ql + qo);
        const unsigned* hu = (const unsigned*)&h4;
        const unsigned* lu = (const unsigned*)&l4;
#pragma unroll
        for (int w = 0; w < 4; w++) {
            qs[i][c8 + 2 * w]     = joinu(hu[w] & 0xFFFFu, lu[w] & 0xFFFFu);
            qs[i][c8 + 2 * w + 1] = joinu(hu[w] >> 16,     lu[w] >> 16);
        }
        size_t ko = qo + 512;
        h4 = *(const uint4*)(qh + ko);
        l4 = *(const uint4*)(ql + ko);
#pragma unroll
        for (int w = 0; w < 4; w++) {
            ks[i][c8 + 2 * w]     = joinu(hu[w] & 0xFFFFu, lu[w] & 0xFFFFu);
            ks[i][c8 + 2 * w + 1] = joinu(hu[w] >> 16,     lu[w] >> 16);
        }
    }
    __syncthreads();

    for (int t = tid; t < 512; t += 256) {
        int h = t >> 6, r = t & 63, i = r >> 3, j = r & 7;
        const float* qp = &qs[i][h * 64];
        const float* kp = &ks[j][h * 64];
        float s = 0.0f;
#pragma unroll
        for (int d = 0; d < 64; d++) s = fmaf(qp[d], kp[d], s);
        sc[h][i][j] = s * 0.125f;
    }
    __syncthreads();

    if (tid < 64) {
        int h = tid >> 3, i = tid & 7;
        float* row = sc[h][i];
        float m = row[0];
#pragma unroll
        for (int j = 1; j < 8; j++) m = fmaxf(m, row[j]);
        float e[8], s = 0.0f;
#pragma unroll
        for (int j = 0; j < 8; j++) { e[j] = expf(row[j] - m); s += e[j]; }
        float inv = 1.0f / s;
#pragma unroll
        for (int j = 0; j < 8; j++) row[j] = e[j] * inv;
    }
    __syncthreads();

    const size_t obase = (size_t)b * 8 * DM;
    for (int t = tid; t < 4096; t += 256) {
        int i = t >> 9, c = t & 511, h = c >> 6;
        const __nv_bfloat16* vh = qh + rbase + 1024 + c;
        const __nv_bfloat16* vl = ql + rbase + 1024 + c;
        const float* ar = sc[h][i];
        float s = 0.0f;
#pragma unroll
        for (int j = 0; j < 8; j++) {
            float vv = join2(vh[(size_t)j * DQKV], vl[(size_t)j * DQKV]);
            s = fmaf(ar[j], vv, s);
        }
        __nv_bfloat16 hi, lo;
        split2(s, hi, lo);
        size_t o = obase + (size_t)i * DM + c;
        ch[o] = hi; cl[o] = lo;
    }
}

// ---------------------------------------------------------------------------
// Layer-2 selected-query attention: qsel [B][512], kv [M][1024] -> ctx [B][512]
// ---------------------------------------------------------------------------
__global__ __launch_bounds__(256)
void attn_sel_kernel(const __nv_bfloat16* __restrict__ qh, const __nv_bfloat16* __restrict__ ql,
                     const __nv_bfloat16* __restrict__ kvh, const __nv_bfloat16* __restrict__ kvl,
                     __nv_bfloat16* __restrict__ ch, __nv_bfloat16* __restrict__ cl) {
    __shared__ float qs[512];
    __shared__ float ks[8][512];
    __shared__ float sc[8][8];          // [head][j]

    const int b = blockIdx.x, tid = threadIdx.x;
    const size_t qbase  = (size_t)b * DM;
    const size_t kvbase = (size_t)b * 8 * 1024;

    for (int t = tid; t < 512; t += 256)
        qs[t] = join2(qh[qbase + t], ql[qbase + t]);
    for (int t = tid; t < 4096; t += 256) {
        int j = t >> 9, c = t & 511;
        size_t o = kvbase + (size_t)j * 1024 + c;
        ks[j][c] = join2(kvh[o], kvl[o]);
    }
    __syncthreads();

    if (tid < 64) {
        int h = tid >> 3, j = tid & 7;
        const float* qp = &qs[h * 64];
        const float* kp = &ks[j][h * 64];
        float s = 0.0f;
#pragma unroll
        for (int d = 0; d < 64; d++) s = fmaf(qp[d], kp[d], s);
        sc[h][j] = s * 0.125f;
    }
    __syncthreads();

    if (tid < 8) {
        float* row = sc[tid];
        float m = row[0];
#pragma unroll
        for (int j = 1; j < 8; j++) m = fmaxf(m, row[j]);
        float e[8], s = 0.0f;
#pragma unroll
        for (int j = 0; j < 8; j++) { e[j] = expf(row[j] - m); s += e[j]; }
        float inv = 1.0f / s;
#pragma unroll
        for (int j = 0; j < 8; j++) row[j] = e[j] * inv;
    }
    __syncthreads();

    for (int t = tid; t < 512; t += 256) {
        int h = t >> 6;
        const float* ar = sc[h];
        float s = 0.0f;
#pragma unroll
        for (int j = 0; j < 8; j++) {
            size_t o = kvbase + (size_t)j * 1024 + 512 + t;
            s = fmaf(ar[j], join2(kvh[o], kvl[o]), s);
        }
        __nv_bfloat16 hi, lo;
        split2(s, hi, lo);
        ch[qbase + t] = hi; cl[qbase + t] = lo;
    }
}

// ---------------------------------------------------------------------------
// Row gather: sel[b][:] = h[b*8 + b%8][:]
// ---------------------------------------------------------------------------
__global__ void selgather_kernel(const __nv_bfloat16* __restrict__ hh,
                                 const __nv_bfloat16* __restrict__ hl,
                                 __nv_bfloat16* __restrict__ sh,
                                 __nv_bfloat16* __restrict__ sl) {
    int t = blockIdx.x * 256 + threadIdx.x;      // < MSEL*DM
    int b = t >> 9, c = t & 511;
    size_t src = ((size_t)b * 8 + (b & 7)) * DM + c;
    sh[t] = hh[src];
    sl[t] = hl[src];
}

// ---------------------------------------------------------------------------
// Residual + LayerNorm -> split planes (in-place on h)
// ---------------------------------------------------------------------------
__global__ __launch_bounds__(128)
void ln_kernel(const __nv_bfloat16* __restrict__ th, const __nv_bfloat16* __restrict__ tl,
               __nv_bfloat16* __restrict__ hh, __nv_bfloat16* __restrict__ hl,
               const float* __restrict__ g, const float* __restrict__ bb) {
    const int row = blockIdx.x, tid = threadIdx.x;
    const size_t base = (size_t)row * DM + tid * 4;

    uint2 t_h = *(const uint2*)(th + base);
    uint2 t_l = *(const uint2*)(tl + base);
    uint2 h_h = *(const uint2*)(hh + base);
    uint2 h_l = *(const uint2*)(hl + base);
    const unsigned* thu = (const unsigned*)&t_h;
    const unsigned* tlu = (const unsigned*)&t_l;
    const unsigned* hhu = (const unsigned*)&h_h;
    const unsigned* hlu = (const unsigned*)&h_l;

    float x[4];
#pragma unroll
    for (int w = 0; w < 2; w++) {
        x[2 * w]     = joinu(thu[w] & 0xFFFFu, tlu[w] & 0xFFFFu) +
                       joinu(hhu[w] & 0xFFFFu, hlu[w] & 0xFFFFu);
        x[2 * w + 1] = joinu(thu[w] >> 16, tlu[w] >> 16) +
                       joinu(hhu[w] >> 16, hlu[w] >> 16);
    }

    float s = x[0] + x[1] + x[2] + x[3];
#pragma unroll
    for (int o = 16; o; o >>= 1) s += __shfl_xor_sync(0xFFFFFFFFu, s, o);

    __shared__ float sm1[4], sm2[4];
    const int w = tid >> 5, lane = tid & 31;
    if (!lane) sm1[w] = s;
    __syncthreads();
    float mu = (sm1[0] + sm1[1] + sm1[2] + sm1[3]) * (1.0f / 512.0f);

    float d0 = x[0] - mu, d1 = x[1] - mu, d2 = x[2] - mu, d3 = x[3] - mu;
    float ss = d0 * d0 + d1 * d1 + d2 * d2 + d3 * d3;
#pragma unroll
    for (int o = 16; o; o >>= 1) ss += __shfl_xor_sync(0xFFFFFFFFu, ss, o);
    if (!lane) sm2[w] = ss;
    __syncthreads();
    float var = (sm2[0] + sm2[1] + sm2[2] + sm2[3]) * (1.0f / 512.0f);
    float inv = rsqrtf(var + LN_EPS);

    float4 gg = ((const float4*)g)[tid];
    float4 bv = ((const float4*)bb)[tid];
    float o0 = d0 * inv * gg.x + bv.x;
    float o1 = d1 * inv * gg.y + bv.y;
    float o2 = d2 * inv * gg.z + bv.z;
    float o3 = d3 * inv * gg.w + bv.w;

    __nv_bfloat16 a0, b0, a1, b1, a2, b2, a3, b3;
    split2(o0, a0, b0); split2(o1, a1, b1);
    split2(o2, a2, b2); split2(o3, a3, b3);
    uint2 oh = make_uint2(packbf(a0, a1), packbf(a2, a3));
    uint2 ol = make_uint2(packbf(b0, b1), packbf(b2, b3));
    *(uint2*)(hh + base) = oh;
    *(uint2*)(hl + base) = ol;
}

// ---------------------------------------------------------------------------
// Final residual + LayerNorm -> fp32 output (layer-2 LN2, fused with gather)
// ---------------------------------------------------------------------------
__global__ __launch_bounds__(128)
void lnout_kernel(const __nv_bfloat16* __restrict__ th, const __nv_bfloat16* __restrict__ tl,
                  const __nv_bfloat16* __restrict__ hh, const __nv_bfloat16* __restrict__ hl,
                  const float* __restrict__ g, const float* __restrict__ bb,
                  float* __restrict__ out) {
    const int row = blockIdx.x, tid = threadIdx.x;
    const size_t base = (size_t)row * DM + tid * 4;

    float x[4];
#pragma unroll
    for (int j = 0; j < 4; j++)
        x[j] = join2(th[base + j], tl[base + j]) + join2(hh[base + j], hl[base + j]);

    float s = x[0] + x[1] + x[2] + x[3];
#pragma unroll
    for (int o = 16; o; o >>= 1) s += __shfl_xor_sync(0xFFFFFFFFu, s, o);

    __shared__ float sm1[4], sm2[4];
    const int w = tid >> 5, lane = tid & 31;
    if (!lane) sm1[w] = s;
    __syncthreads();
    float mu = (sm1[0] + sm1[1] + sm1[2] + sm1[3]) * (1.0f / 512.0f);

    float d0 = x[0] - mu, d1 = x[1] - mu, d2 = x[2] - mu, d3 = x[3] - mu;
    float ss = d0 * d0 + d1 * d1 + d2 * d2 + d3 * d3;
#pragma unroll
    for (int o = 16; o; o >>= 1) ss += __shfl_xor_sync(0xFFFFFFFFu, ss, o);
    if (!lane) sm2[w] = ss;
    __syncthreads();
    float var = (sm2[0] + sm2[1] + sm2[2] + sm2[3]) * (1.0f / 512.0f);
    float inv = rsqrtf(var + LN_EPS);

    float4 gg = ((const float4*)g)[tid];
    float4 bv = ((const float4*)bb)[tid];
    float4 o4;
    o4.x = d0 * inv * gg.x + bv.x;
    o4.y = d1 * inv * gg.y + bv.y;
    o4.z = d2 * inv * gg.z + bv.z;
    o4.w = d3 * inv * gg.w + bv.w;
    *(float4*)(out + base) = o4;
}

// ---------------------------------------------------------------------------
// Launch
// ---------------------------------------------------------------------------
extern "C" void kernel_launch(void* const* d_in, const int* in_sizes, int n_in,
                              void* d_out, int out_size) {
    const float* x    = (const float*)d_in[0];
    const float* Wq   = (const float*)d_in[1];
    const float* bq   = (const float*)d_in[2];
    const float* Wk   = (const float*)d_in[3];
    const float* bk   = (const float*)d_in[4];
    const float* Wv   = (const float*)d_in[5];
    const float* bv   = (const float*)d_in[6];
    const float* Wo   = (const float*)d_in[7];
    const float* bo   = (const float*)d_in[8];
    const float* ln1g = (const float*)d_in[9];
    const float* ln1b = (const float*)d_in[10];
    const float* W1   = (const float*)d_in[11];
    const float* b1   = (const float*)d_in[12];
    const float* W2   = (const float*)d_in[13];
    const float* b2   = (const float*)d_in[14];
    const float* ln2g = (const float*)d_in[15];
    const float* ln2b = (const float*)d_in[16];
    float* out = (float*)d_out;

    __nv_bfloat16 *h_hi, *h_lo, *qkv_hi, *qkv_lo, *ctx_hi, *ctx_lo,
                  *t_hi, *t_lo, *mid_hi, *mid_lo,
                  *sh_hi, *sh_lo, *qs_hi, *qs_lo,
                  *wqkvT_hi, *wqkvT_lo, *woT_hi, *woT_lo,
                  *w1T_hi, *w1T_lo, *w2T_hi, *w2T_lo;
    float* bqkv;
    cudaGetSymbolAddress((void**)&h_hi, g_h_hi);     cudaGetSymbolAddress((void**)&h_lo, g_h_lo);
    cudaGetSymbolAddress((void**)&qkv_hi, g_qkv_hi); cudaGetSymbolAddress((void**)&qkv_lo, g_qkv_lo);
    cudaGetSymbolAddress((void**)&ctx_hi, g_ctx_hi); cudaGetSymbolAddress((void**)&ctx_lo, g_ctx_lo);
    cudaGetSymbolAddress((void**)&t_hi, g_t_hi);     cudaGetSymbolAddress((void**)&t_lo, g_t_lo);
    cudaGetSymbolAddress((void**)&mid_hi, g_mid_hi); cudaGetSymbolAddress((void**)&mid_lo, g_mid_lo);
    cudaGetSymbolAddress((void**)&sh_hi, g_sh_hi);   cudaGetSymbolAddress((void**)&sh_lo, g_sh_lo);
    cudaGetSymbolAddress((void**)&qs_hi, g_qs_hi);   cudaGetSymbolAddress((void**)&qs_lo, g_qs_lo);
    cudaGetSymbolAddress((void**)&wqkvT_hi, g_wqkvT_hi); cudaGetSymbolAddress((void**)&wqkvT_lo, g_wqkvT_lo);
    cudaGetSymbolAddress((void**)&woT_hi, g_woT_hi); cudaGetSymbolAddress((void**)&woT_lo, g_woT_lo);
    cudaGetSymbolAddress((void**)&w1T_hi, g_w1T_hi); cudaGetSymbolAddress((void**)&w1T_lo, g_w1T_lo);
    cudaGetSymbolAddress((void**)&w2T_hi, g_w2T_hi); cudaGetSymbolAddress((void**)&w2T_lo, g_w2T_lo);
    cudaGetSymbolAddress((void**)&bqkv, g_bqkv);

    cudaFuncSetAttribute(gemm_wmma, cudaFuncAttributeMaxDynamicSharedMemorySize, GSMEM);

    // h = split(x + pos)
    pos_kernel<<<(MTOK * DM) / 256, 256>>>(x, h_hi, h_lo);

    // =========================== Layer 0 (full) ===========================
    {
        const int l = 0;
        const size_t oW  = (size_t)l * DM * DM;
        const size_t oV  = (size_t)l * DM;
        const size_t oW1 = (size_t)l * DM * DH;
        const size_t oB1 = (size_t)l * DH;
        const size_t oW2 = (size_t)l * DH * DM;

        wsplit_kernel<<<dim3(16, 16), 256>>>(Wq + oW, DM, DM, wqkvT_hi, wqkvT_lo, 0);
        wsplit_kernel<<<dim3(16, 16), 256>>>(Wk + oW, DM, DM, wqkvT_hi, wqkvT_lo, 512);
        wsplit_kernel<<<dim3(16, 16), 256>>>(Wv + oW, DM, DM, wqkvT_hi, wqkvT_lo, 1024);
        bcat_kernel<<<6, 256>>>(bq + oV, bk + oV, bv + oV, bqkv);
        wsplit_kernel<<<dim3(16, 16), 256>>>(Wo + oW, DM, DM, woT_hi, woT_lo, 0);
        wsplit_kernel<<<dim3(64, 16), 256>>>(W1 + oW1, DM, DH, w1T_hi, w1T_lo, 0);
        wsplit_kernel<<<dim3(16, 64), 256>>>(W2 + oW2, DH, DM, w2T_hi, w2T_lo, 0);

        gemm_wmma<<<dim3(DQKV / BN, MTOK / BM), 256, GSMEM>>>(
            h_hi, h_lo, wqkvT_hi, wqkvT_lo, bqkv, qkv_hi, qkv_lo, DQKV, DM, 0);
        attn_kernel<<<BATCH, 256>>>(qkv_hi, qkv_lo, ctx_hi, ctx_lo);
        gemm_wmma<<<dim3(DM / BN, MTOK / BM), 256, GSMEM>>>(
            ctx_hi, ctx_lo, woT_hi, woT_lo, bo + oV, t_hi, t_lo, DM, DM, 0);
        ln_kernel<<<MTOK, 128>>>(t_hi, t_lo, h_hi, h_lo, ln1g + oV, ln1b + oV);
        gemm_wmma<<<dim3(DH / BN, MTOK / BM), 256, GSMEM>>>(
            h_hi, h_lo, w1T_hi, w1T_lo, b1 + oB1, mid_hi, mid_lo, DH, DM, 1);
        gemm_wmma<<<dim3(DM / BN, MTOK / BM), 256, GSMEM>>>(
            mid_hi, mid_lo, w2T_hi, w2T_lo, b2 + oV, t_hi, t_lo, DM, DH, 0);
        ln_kernel<<<MTOK, 128>>>(t_hi, t_lo, h_hi, h_lo, ln2g + oV, ln2b + oV);
    }

    // =================== Layer 1 (selected-token compact) ===================
    {
        const int l = 1;
        const size_t oW  = (size_t)l * DM * DM;
        const size_t oV  = (size_t)l * DM;
        const size_t oW1 = (size_t)l * DM * DH;
        const size_t oB1 = (size_t)l * DH;
        const size_t oW2 = (size_t)l * DH * DM;

        wsplit_kernel<<<dim3(16, 16), 256>>>(Wq + oW, DM, DM, wqkvT_hi, wqkvT_lo, 0);
        wsplit_kernel<<<dim3(16, 16), 256>>>(Wk + oW, DM, DM, wqkvT_hi, wqkvT_lo, 512);
        wsplit_kernel<<<dim3(16, 16), 256>>>(Wv + oW, DM, DM, wqkvT_hi, wqkvT_lo, 1024);
        bcat_kernel<<<6, 256>>>(bq + oV, bk + oV, bv + oV, bqkv);
        wsplit_kernel<<<dim3(16, 16), 256>>>(Wo + oW, DM, DM, woT_hi, woT_lo, 0);
        wsplit_kernel<<<dim3(64, 16), 256>>>(W1 + oW1, DM, DH, w1T_hi, w1T_lo, 0);
        wsplit_kernel<<<dim3(16, 64), 256>>>(W2 + oW2, DH, DM, w2T_hi, w2T_lo, 0);

        // KV projection over ALL tokens: [M,512] @ [512,1024] (wqkvT rows 512..1535)
        gemm_wmma<<<dim3(1024 / BN, MTOK / BM), 256, GSMEM>>>(
            h_hi, h_lo, wqkvT_hi + (size_t)512 * DM, wqkvT_lo + (size_t)512 * DM,
            bqkv + 512, qkv_hi, qkv_lo, 1024, DM, 0);

        // gather selected rows of h, project Q only for those
        selgather_kernel<<<(MSEL * DM) / 256, 256>>>(h_hi, h_lo, sh_hi, sh_lo);
        gemm_wmma<<<dim3(DM / BN, MSEL / BM), 256, GSMEM>>>(
            sh_hi, sh_lo, wqkvT_hi, wqkvT_lo, bqkv, qs_hi, qs_lo, DM, DM, 0);

        // 1-query attention per batch
        attn_sel_kernel<<<BATCH, 256>>>(qs_hi, qs_lo, qkv_hi, qkv_lo, ctx_hi, ctx_lo);

        // O-projection + LN1 on 16384 rows
        gemm_wmma<<<dim3(DM / BN, MSEL / BM), 256, GSMEM>>>(
            ctx_hi, ctx_lo, woT_hi, woT_lo, bo + oV, t_hi, t_lo, DM, DM, 0);
        ln_kernel<<<MSEL, 128>>>(t_hi, t_lo, sh_hi, sh_lo, ln1g + oV, ln1b + oV);

        // FFN on 16384 rows, final LN2 -> fp32 out (gather already applied)
        gemm_wmma<<<dim3(DH / BN, MSEL / BM), 256, GSMEM>>>(
            sh_hi, sh_lo, w1T_hi, w1T_lo, b1 + oB1, mid_hi, mid_lo, DH, DM, 1);
        gemm_wmma<<<dim3(DM / BN, MSEL / BM), 256, GSMEM>>>(
            mid_hi, mid_lo, w2T_hi, w2T_lo, b2 + oV, t_hi, t_lo, DM, DH, 0);
        lnout_kernel<<<MSEL, 128>>>(t_hi, t_lo, sh_hi, sh_lo, ln2g + oV, ln2b + oV, out);
    }
}

// round 10
// speedup vs baseline: 5.3394x; 1.2218x over previous
#include <cuda_runtime.h>
#include <cuda_bf16.h>
#include <mma.h>
#include <cstdint>
#include <math.h>

using namespace nvcuda;

// ---------------------------------------------------------------------------
// Problem constants
// ---------------------------------------------------------------------------
#define BATCH   16384
#define SEQ     8
#define MTOK    (BATCH * SEQ)     // 131072 token rows
#define MSEL    BATCH             // 16384 selected rows (layer 2 compact path)
#define DM      512
#define DH      2048
#define DQKV    1536              // fused q|k|v width (layer 1)
#define LN_EPS  1e-6f

// GEMM tiling
#define BM      128
#define BN      128
#define BK      32
#define SSTRIDE 40                               // smem row stride in bf16 elems (80B)
#define PLANE_BYTES (128 * SSTRIDE * 2)          // 10240
#define STAGE_BYTES (4u * PLANE_BYTES)           // 40960: Ahi|Alo|Bhi|Blo
#define CSTRIDE 136                              // epilogue fp32 stride (544B)
#define GSMEM   (2u * STAGE_BYTES)               // 81920 (epilogue needs 69632)

// ---------------------------------------------------------------------------
// Scratch (device globals = legal scratch)
// ---------------------------------------------------------------------------
__device__ __nv_bfloat16 g_h_hi  [(size_t)MTOK * DM];
__device__ __nv_bfloat16 g_h_lo  [(size_t)MTOK * DM];
__device__ __nv_bfloat16 g_qkv_hi[(size_t)MTOK * DQKV];   // L1: qkv. L2: kv [M][1024]
__device__ __nv_bfloat16 g_qkv_lo[(size_t)MTOK * DQKV];
__device__ __nv_bfloat16 g_ctx_hi[(size_t)MTOK * DM];
__device__ __nv_bfloat16 g_ctx_lo[(size_t)MTOK * DM];
__device__ __nv_bfloat16 g_t_hi  [(size_t)MTOK * DM];
__device__ __nv_bfloat16 g_t_lo  [(size_t)MTOK * DM];
__device__ __nv_bfloat16 g_mid_hi[(size_t)MTOK * DH];
__device__ __nv_bfloat16 g_mid_lo[(size_t)MTOK * DH];
// layer-2 compact buffers
__device__ __nv_bfloat16 g_sh_hi [(size_t)MSEL * DM];     // selected h rows
__device__ __nv_bfloat16 g_sh_lo [(size_t)MSEL * DM];
__device__ __nv_bfloat16 g_qs_hi [(size_t)MSEL * DM];     // selected q
__device__ __nv_bfloat16 g_qs_lo [(size_t)MSEL * DM];
// split-transposed weights, both layers resident (prep all up front)
__device__ __nv_bfloat16 g_wqkvT_hi[2][(size_t)DQKV * DM];
__device__ __nv_bfloat16 g_wqkvT_lo[2][(size_t)DQKV * DM];
__device__ __nv_bfloat16 g_woT_hi  [2][(size_t)DM * DM];
__device__ __nv_bfloat16 g_woT_lo  [2][(size_t)DM * DM];
__device__ __nv_bfloat16 g_w1T_hi  [2][(size_t)DH * DM];
__device__ __nv_bfloat16 g_w1T_lo  [2][(size_t)DH * DM];
__device__ __nv_bfloat16 g_w2T_hi  [2][(size_t)DM * DH];
__device__ __nv_bfloat16 g_w2T_lo  [2][(size_t)DM * DH];
__device__ float         g_bqkv   [2][DQKV];

// ---------------------------------------------------------------------------
// Helpers
// ---------------------------------------------------------------------------
__device__ __forceinline__ uint32_t smem_u32(const void* p) {
    uint32_t a;
    asm("{ .reg .u64 t; cvta.to.shared.u64 t, %1; cvt.u32.u64 %0, t; }" : "=r"(a) : "l"(p));
    return a;
}
__device__ __forceinline__ void cp16(uint32_t sm, const void* g) {
    asm volatile("cp.async.cg.shared.global [%0], [%1], 16;" :: "r"(sm), "l"(g));
}
__device__ __forceinline__ void split2(float x, __nv_bfloat16& hi, __nv_bfloat16& lo) {
    hi = __float2bfloat16(x);
    lo = __float2bfloat16(x - __bfloat162float(hi));
}
__device__ __forceinline__ float join2(__nv_bfloat16 hi, __nv_bfloat16 lo) {
    return __bfloat162float(hi) + __bfloat162float(lo);
}
__device__ __forceinline__ float joinu(uint32_t h, uint32_t l) {
    return __bfloat162float(__ushort_as_bfloat16((unsigned short)h)) +
           __bfloat162float(__ushort_as_bfloat16((unsigned short)l));
}
__device__ __forceinline__ unsigned packbf(__nv_bfloat16 a, __nv_bfloat16 b) {
    return (unsigned)__bfloat16_as_ushort(a) | ((unsigned)__bfloat16_as_ushort(b) << 16);
}

// ---------------------------------------------------------------------------
// wmma tensor-core GEMM. NEW: __launch_bounds__(256, 2) forces <=128 regs so
// two 81,920B-smem CTAs co-reside per SM (163,840B < 228KB carveout).
// ---------------------------------------------------------------------------
__global__ __launch_bounds__(256, 2)
void gemm_wmma(const __nv_bfloat16* __restrict__ Ahi, const __nv_bfloat16* __restrict__ Alo,
               const __nv_bfloat16* __restrict__ Bhi, const __nv_bfloat16* __restrict__ Blo,
               const float* __restrict__ bias,
               __nv_bfloat16* __restrict__ Chi, __nv_bfloat16* __restrict__ Clo,
               int N, int K, int relu)
{
    extern __shared__ char smem[];
    const uint32_t sb = smem_u32(smem);
    const int tid = threadIdx.x;
    const int wid = tid >> 5;
    const int wy  = wid & 3;
    const int wx  = wid >> 2;
    const int m0  = blockIdx.y << 7;
    const int n0  = blockIdx.x << 7;
    const int NC  = K / BK;

    wmma::fragment<wmma::accumulator, 16, 16, 16, float> acc[2][4];
#pragma unroll
    for (int m = 0; m < 2; m++)
#pragma unroll
        for (int n = 0; n < 4; n++) wmma::fill_fragment(acc[m][n], 0.0f);

    auto load_stage = [&](int st, int k0) {
        const uint32_t base = sb + (uint32_t)st * STAGE_BYTES;
        for (int i = tid; i < 2048; i += 256) {
            const int plane = i >> 9;
            const int r     = (i >> 2) & 127;
            const int c     = (i & 3) << 4;
            const uint32_t saddr = base + (uint32_t)plane * PLANE_BYTES
                                 + (uint32_t)r * (SSTRIDE * 2) + c;
            const __nv_bfloat16* gp;
            if      (plane == 0) gp = Ahi + (size_t)(m0 + r) * K + k0;
            else if (plane == 1) gp = Alo + (size_t)(m0 + r) * K + k0;
            else if (plane == 2) gp = Bhi + (size_t)(n0 + r) * K + k0;
            else                 gp = Blo + (size_t)(n0 + r) * K + k0;
            cp16(saddr, (const char*)gp + c);
        }
        asm volatile("cp.async.commit_group;" ::: "memory");
    };

    load_stage(0, 0);

    for (int ch = 0; ch < NC; ch++) {
        if (ch + 1 < NC) {
            load_stage((ch + 1) & 1, (ch + 1) * BK);
            asm volatile("cp.async.wait_group 1;" ::: "memory");
        } else {
            asm volatile("cp.async.wait_group 0;" ::: "memory");
        }
        __syncthreads();

        const __nv_bfloat16* ss =
            (const __nv_bfloat16*)(smem + (size_t)(ch & 1) * STAGE_BYTES);
        const __nv_bfloat16* sAhi = ss;
        const __nv_bfloat16* sAlo = ss + 128 * SSTRIDE;
        const __nv_bfloat16* sBhi = ss + 2 * 128 * SSTRIDE;
        const __nv_bfloat16* sBlo = ss + 3 * 128 * SSTRIDE;

#pragma unroll
        for (int ks = 0; ks < 2; ks++) {
            wmma::fragment<wmma::matrix_a, 16, 16, 16, __nv_bfloat16, wmma::row_major> ah[2], al[2];
#pragma unroll
            for (int m = 0; m < 2; m++) {
                const int row = wy * 32 + m * 16;
                wmma::load_matrix_sync(ah[m], sAhi + row * SSTRIDE + ks * 16, SSTRIDE);
                wmma::load_matrix_sync(al[m], sAlo + row * SSTRIDE + ks * 16, SSTRIDE);
            }
#pragma unroll
            for (int n = 0; n < 4; n++) {
                const int col = wx * 64 + n * 16;
                wmma::fragment<wmma::matrix_b, 16, 16, 16, __nv_bfloat16, wmma::col_major> bh, bl;
                wmma::load_matrix_sync(bh, sBhi + col * SSTRIDE + ks * 16, SSTRIDE);
                wmma::load_matrix_sync(bl, sBlo + col * SSTRIDE + ks * 16, SSTRIDE);
#pragma unroll
                for (int m = 0; m < 2; m++) {
                    wmma::mma_sync(acc[m][n], ah[m], bh, acc[m][n]);
                    wmma::mma_sync(acc[m][n], ah[m], bl, acc[m][n]);
                    wmma::mma_sync(acc[m][n], al[m], bh, acc[m][n]);
                }
            }
        }
        __syncthreads();
    }

    float* cs = (float*)smem;
#pragma unroll
    for (int m = 0; m < 2; m++)
#pragma unroll
        for (int n = 0; n < 4; n++)
            wmma::store_matrix_sync(cs + (size_t)(wy * 32 + m * 16) * CSTRIDE
                                       + wx * 64 + n * 16,
                                    acc[m][n], CSTRIDE, wmma::mem_row_major);
    __syncthreads();

    {
        const int r    = tid >> 1;
        const int half = tid & 1;
        const int row  = m0 + r;
        const int cb   = half * 64;
        const float* src = cs + (size_t)r * CSTRIDE + cb;
        __nv_bfloat16* dh = Chi + (size_t)row * N + n0 + cb;
        __nv_bfloat16* dl = Clo + (size_t)row * N + n0 + cb;
        const float* bp = bias + n0 + cb;
#pragma unroll
        for (int g = 0; g < 8; g++) {
            unsigned hw[4], lw[4];
#pragma unroll
            for (int j = 0; j < 4; j++) {
                float v0 = src[g * 8 + 2 * j]     + bp[g * 8 + 2 * j];
                float v1 = src[g * 8 + 2 * j + 1] + bp[g * 8 + 2 * j + 1];
                if (relu) { v0 = fmaxf(v0, 0.0f); v1 = fmaxf(v1, 0.0f); }
                __nv_bfloat16 h0, l0, h1, l1;
                split2(v0, h0, l0);
                split2(v1, h1, l1);
                hw[j] = packbf(h0, h1);
                lw[j] = packbf(l0, l1);
            }
            *(uint4*)(dh + g * 8) = *(const uint4*)hw;
            *(uint4*)(dl + g * 8) = *(const uint4*)lw;
        }
    }
}

// ---------------------------------------------------------------------------
// Fused weight prep for one layer: all 6 matrices split+transposed in ONE
// launch (3072 blocks). Replaces 7 wsplit launches.
// Block map: [0,768) Wq|Wk|Wv -> wqkvT ; [768,1024) Wo ; [1024,2048) W1 ;
//            [2048,3072) W2.
// ---------------------------------------------------------------------------
__global__ __launch_bounds__(256)
void wprep_kernel(const float* __restrict__ Wq, const float* __restrict__ Wk,
                  const float* __restrict__ Wv, const float* __restrict__ Wo,
                  const float* __restrict__ W1, const float* __restrict__ W2,
                  __nv_bfloat16* __restrict__ qkvThi, __nv_bfloat16* __restrict__ qkvTlo,
                  __nv_bfloat16* __restrict__ woThi,  __nv_bfloat16* __restrict__ woTlo,
                  __nv_bfloat16* __restrict__ w1Thi,  __nv_bfloat16* __restrict__ w1Tlo,
                  __nv_bfloat16* __restrict__ w2Thi,  __nv_bfloat16* __restrict__ w2Tlo)
{
    __shared__ float tile[32][33];
    const int t = blockIdx.x;
    const float* W; int K, N, rowOff, bx, by;
    __nv_bfloat16 *Thi, *Tlo;

    if (t < 768) {                    // Wq/Wk/Wv -> fused qkvT
        const int g = t >> 8, r = t & 255;
        W = (g == 0) ? Wq : (g == 1) ? Wk : Wv;
        K = DM; N = DM; rowOff = g * DM;
        bx = r & 15; by = r >> 4;
        Thi = qkvThi; Tlo = qkvTlo;
    } else if (t < 1024) {            // Wo
        const int r = t - 768;
        W = Wo; K = DM; N = DM; rowOff = 0;
        bx = r & 15; by = r >> 4;
        Thi = woThi; Tlo = woTlo;
    } else if (t < 2048) {            // W1: [512,2048] -> 64 x 16 tiles
        const int r = t - 1024;
        W = W1; K = DM; N = DH; rowOff = 0;
        bx = r & 63; by = r >> 6;
        Thi = w1Thi; Tlo = w1Tlo;
    } else {                          // W2: [2048,512] -> 16 x 64 tiles
        const int r = t - 2048;
        W = W2; K = DH; N = DM; rowOff = 0;
        bx = r & 15; by = r >> 4;
        Thi = w2Thi; Tlo = w2Tlo;
    }

    const int tx = threadIdx.x & 31, ty = threadIdx.x >> 5;
    const int n0 = bx << 5, k0 = by << 5;
#pragma unroll
    for (int r = 0; r < 4; r++) {
        int k = k0 + ty + r * 8;
        tile[ty + r * 8][tx] = W[(size_t)k * N + n0 + tx];
    }
    __syncthreads();
#pragma unroll
    for (int r = 0; r < 4; r++) {
        int n = n0 + ty + r * 8;
        float v = tile[tx][ty + r * 8];
        __nv_bfloat16 hi, lo;
        split2(v, hi, lo);
        size_t o = (size_t)(rowOff + n) * K + k0 + tx;
        Thi[o] = hi; Tlo[o] = lo;
    }
}

__global__ void bcat_kernel(const float* __restrict__ a, const float* __restrict__ b,
                            const float* __restrict__ c, float* __restrict__ o) {
    int t = blockIdx.x * 256 + threadIdx.x;
    if (t < 512) o[t] = a[t];
    else if (t < 1024) o[t] = b[t - 512];
    else if (t < 1536) o[t] = c[t - 1024];
}

// ---------------------------------------------------------------------------
// Positional encoding: h = split(x + sinusoid)
// ---------------------------------------------------------------------------
__global__ void pos_kernel(const float* __restrict__ x,
                           __nv_bfloat16* __restrict__ hhi, __nv_bfloat16* __restrict__ hlo) {
    int t = blockIdx.x * 256 + threadIdx.x;
    int c = t & 511;
    int s = (t >> 9) & 7;
    int d2 = c >> 1;
    float e = (float)(2 * d2) * (1.0f / 512.0f);
    float ang = (float)s * powf(10000.0f, -e);
    float p = (c & 1) ? cosf(ang) : sinf(ang);
    __nv_bfloat16 hi, lo;
    split2(x[t] + p, hi, lo);
    hhi[t] = hi; hlo[t] = lo;
}

// ---------------------------------------------------------------------------
// Layer-1 attention: qkv fused planes [M][1536] -> ctx planes [M][512]
// ---------------------------------------------------------------------------
__global__ __launch_bounds__(256)
void attn_kernel(const __nv_bfloat16* __restrict__ qh, const __nv_bfloat16* __restrict__ ql,
                 __nv_bfloat16* __restrict__ ch, __nv_bfloat16* __restrict__ cl) {
    __shared__ float qs[8][512];
    __shared__ float ks[8][512];
    __shared__ float sc[8][8][8];

    const int b = blockIdx.x, tid = threadIdx.x;
    const size_t rbase = (size_t)b * 8 * DQKV;

    for (int t = tid; t < 512; t += 256) {
        int i = t >> 6;
        int c8 = (t & 63) << 3;
        size_t qo = rbase + (size_t)i * DQKV + c8;
        uint4 h4 = *(const uint4*)(qh + qo);
        uint4 l4 = *(const uint4*)(ql + qo);
        const unsigned* hu = (const unsigned*)&h4;
        const unsigned* lu = (const unsigned*)&l4;
#pragma unroll
        for (int w = 0; w < 4; w++) {
            qs[i][c8 + 2 * w]     = joinu(hu[w] & 0xFFFFu, lu[w] & 0xFFFFu);
            qs[i][c8 + 2 * w + 1] = joinu(hu[w] >> 16,     lu[w] >> 16);
        }
        size_t ko = qo + 512;
        h4 = *(const uint4*)(qh + ko);
        l4 = *(const uint4*)(ql + ko);
#pragma unroll
        for (int w = 0; w < 4; w++) {
            ks[i][c8 + 2 * w]     = joinu(hu[w] & 0xFFFFu, lu[w] & 0xFFFFu);
            ks[i][c8 + 2 * w + 1] = joinu(hu[w] >> 16,     lu[w] >> 16);
        }
    }
    __syncthreads();

    for (int t = tid; t < 512; t += 256) {
        int h = t >> 6, r = t & 63, i = r >> 3, j = r & 7;
        const float* qp = &qs[i][h * 64];
        const float* kp = &ks[j][h * 64];
        float s = 0.0f;
#pragma unroll
        for (int d = 0; d < 64; d++) s = fmaf(qp[d], kp[d], s);
        sc[h][i][j] = s * 0.125f;
    }
    __syncthreads();

    if (tid < 64) {
        int h = tid >> 3, i = tid & 7;
        float* row = sc[h][i];
        float m = row[0];
#pragma unroll
        for (int j = 1; j < 8; j++) m = fmaxf(m, row[j]);
        float e[8], s = 0.0f;
#pragma unroll
        for (int j = 0; j < 8; j++) { e[j] = expf(row[j] - m); s += e[j]; }
        float inv = 1.0f / s;
#pragma unroll
        for (int j = 0; j < 8; j++) row[j] = e[j] * inv;
    }
    __syncthreads();

    const size_t obase = (size_t)b * 8 * DM;
    for (int t = tid; t < 4096; t += 256) {
        int i = t >> 9, c = t & 511, h = c >> 6;
        const __nv_bfloat16* vh = qh + rbase + 1024 + c;
        const __nv_bfloat16* vl = ql + rbase + 1024 + c;
        const float* ar = sc[h][i];
        float s = 0.0f;
#pragma unroll
        for (int j = 0; j < 8; j++) {
            float vv = join2(vh[(size_t)j * DQKV], vl[(size_t)j * DQKV]);
            s = fmaf(ar[j], vv, s);
        }
        __nv_bfloat16 hi, lo;
        split2(s, hi, lo);
        size_t o = obase + (size_t)i * DM + c;
        ch[o] = hi; cl[o] = lo;
    }
}

// ---------------------------------------------------------------------------
// Layer-2 selected-query attention: qsel [B][512], kv [M][1024] -> ctx [B][512]
// ---------------------------------------------------------------------------
__global__ __launch_bounds__(256)
void attn_sel_kernel(const __nv_bfloat16* __restrict__ qh, const __nv_bfloat16* __restrict__ ql,
                     const __nv_bfloat16* __restrict__ kvh, const __nv_bfloat16* __restrict__ kvl,
                     __nv_bfloat16* __restrict__ ch, __nv_bfloat16* __restrict__ cl) {
    __shared__ float qs[512];
    __shared__ float ks[8][512];
    __shared__ float sc[8][8];          // [head][j]

    const int b = blockIdx.x, tid = threadIdx.x;
    const size_t qbase  = (size_t)b * DM;
    const size_t kvbase = (size_t)b * 8 * 1024;

    for (int t = tid; t < 512; t += 256)
        qs[t] = join2(qh[qbase + t], ql[qbase + t]);
    for (int t = tid; t < 4096; t += 256) {
        int j = t >> 9, c = t & 511;
        size_t o = kvbase + (size_t)j * 1024 + c;
        ks[j][c] = join2(kvh[o], kvl[o]);
    }
    __syncthreads();

    if (tid < 64) {
        int h = tid >> 3, j = tid & 7;
        const float* qp = &qs[h * 64];
        const float* kp = &ks[j][h * 64];
        float s = 0.0f;
#pragma unroll
        for (int d = 0; d < 64; d++) s = fmaf(qp[d], kp[d], s);
        sc[h][j] = s * 0.125f;
    }
    __syncthreads();

    if (tid < 8) {
        float* row = sc[tid];
        float m = row[0];
#pragma unroll
        for (int j = 1; j < 8; j++) m = fmaxf(m, row[j]);
        float e[8], s = 0.0f;
#pragma unroll
        for (int j = 0; j < 8; j++) { e[j] = expf(row[j] - m); s += e[j]; }
        float inv = 1.0f / s;
#pragma unroll
        for (int j = 0; j < 8; j++) row[j] = e[j] * inv;
    }
    __syncthreads();

    for (int t = tid; t < 512; t += 256) {
        int h = t >> 6;
        const float* ar = sc[h];
        float s = 0.0f;
#pragma unroll
        for (int j = 0; j < 8; j++) {
            size_t o = kvbase + (size_t)j * 1024 + 512 + t;
            s = fmaf(ar[j], join2(kvh[o], kvl[o]), s);
        }
        __nv_bfloat16 hi, lo;
        split2(s, hi, lo);
        ch[qbase + t] = hi; cl[qbase + t] = lo;
    }
}

// ---------------------------------------------------------------------------
// Row gather: sel[b][:] = h[b*8 + b%8][:]
// ---------------------------------------------------------------------------
__global__ void selgather_kernel(const __nv_bfloat16* __restrict__ hh,
                                 const __nv_bfloat16* __restrict__ hl,
                                 __nv_bfloat16* __restrict__ sh,
                                 __nv_bfloat16* __restrict__ sl) {
    int t = blockIdx.x * 256 + threadIdx.x;      // < MSEL*DM
    int b = t >> 9, c = t & 511;
    size_t src = ((size_t)b * 8 + (b & 7)) * DM + c;
    sh[t] = hh[src];
    sl[t] = hl[src];
}

// ---------------------------------------------------------------------------
// Residual + LayerNorm -> split planes (in-place on h)
// ---------------------------------------------------------------------------
__global__ __launch_bounds__(128)
void ln_kernel(const __nv_bfloat16* __restrict__ th, const __nv_bfloat16* __restrict__ tl,
               __nv_bfloat16* __restrict__ hh, __nv_bfloat16* __restrict__ hl,
               const float* __restrict__ g, const float* __restrict__ bb) {
    const int row = blockIdx.x, tid = threadIdx.x;
    const size_t base = (size_t)row * DM + tid * 4;

    uint2 t_h = *(const uint2*)(th + base);
    uint2 t_l = *(const uint2*)(tl + base);
    uint2 h_h = *(const uint2*)(hh + base);
    uint2 h_l = *(const uint2*)(hl + base);
    const unsigned* thu = (const unsigned*)&t_h;
    const unsigned* tlu = (const unsigned*)&t_l;
    const unsigned* hhu = (const unsigned*)&h_h;
    const unsigned* hlu = (const unsigned*)&h_l;

    float x[4];
#pragma unroll
    for (int w = 0; w < 2; w++) {
        x[2 * w]     = joinu(thu[w] & 0xFFFFu, tlu[w] & 0xFFFFu) +
                       joinu(hhu[w] & 0xFFFFu, hlu[w] & 0xFFFFu);
        x[2 * w + 1] = joinu(thu[w] >> 16, tlu[w] >> 16) +
                       joinu(hhu[w] >> 16, hlu[w] >> 16);
    }

    float s = x[0] + x[1] + x[2] + x[3];
#pragma unroll
    for (int o = 16; o; o >>= 1) s += __shfl_xor_sync(0xFFFFFFFFu, s, o);

    __shared__ float sm1[4], sm2[4];
    const int w = tid >> 5, lane = tid & 31;
    if (!lane) sm1[w] = s;
    __syncthreads();
    float mu = (sm1[0] + sm1[1] + sm1[2] + sm1[3]) * (1.0f / 512.0f);

    float d0 = x[0] - mu, d1 = x[1] - mu, d2 = x[2] - mu, d3 = x[3] - mu;
    float ss = d0 * d0 + d1 * d1 + d2 * d2 + d3 * d3;
#pragma unroll
    for (int o = 16; o; o >>= 1) ss += __shfl_xor_sync(0xFFFFFFFFu, ss, o);
    if (!lane) sm2[w] = ss;
    __syncthreads();
    float var = (sm2[0] + sm2[1] + sm2[2] + sm2[3]) * (1.0f / 512.0f);
    float inv = rsqrtf(var + LN_EPS);

    float4 gg = ((const float4*)g)[tid];
    float4 bv = ((const float4*)bb)[tid];
    float o0 = d0 * inv * gg.x + bv.x;
    float o1 = d1 * inv * gg.y + bv.y;
    float o2 = d2 * inv * gg.z + bv.z;
    float o3 = d3 * inv * gg.w + bv.w;

    __nv_bfloat16 a0, b0, a1, b1, a2, b2, a3, b3;
    split2(o0, a0, b0); split2(o1, a1, b1);
    split2(o2, a2, b2); split2(o3, a3, b3);
    uint2 oh = make_uint2(packbf(a0, a1), packbf(a2, a3));
    uint2 ol = make_uint2(packbf(b0, b1), packbf(b2, b3));
    *(uint2*)(hh + base) = oh;
    *(uint2*)(hl + base) = ol;
}

// ---------------------------------------------------------------------------
// Final residual + LayerNorm -> fp32 output (layer-2 LN2, fused with gather)
// ---------------------------------------------------------------------------
__global__ __launch_bounds__(128)
void lnout_kernel(const __nv_bfloat16* __restrict__ th, const __nv_bfloat16* __restrict__ tl,
                  const __nv_bfloat16* __restrict__ hh, const __nv_bfloat16* __restrict__ hl,
                  const float* __restrict__ g, const float* __restrict__ bb,
                  float* __restrict__ out) {
    const int row = blockIdx.x, tid = threadIdx.x;
    const size_t base = (size_t)row * DM + tid * 4;

    float x[4];
#pragma unroll
    for (int j = 0; j < 4; j++)
        x[j] = join2(th[base + j], tl[base + j]) + join2(hh[base + j], hl[base + j]);

    float s = x[0] + x[1] + x[2] + x[3];
#pragma unroll
    for (int o = 16; o; o >>= 1) s += __shfl_xor_sync(0xFFFFFFFFu, s, o);

    __shared__ float sm1[4], sm2[4];
    const int w = tid >> 5, lane = tid & 31;
    if (!lane) sm1[w] = s;
    __syncthreads();
    float mu = (sm1[0] + sm1[1] + sm1[2] + sm1[3]) * (1.0f / 512.0f);

    float d0 = x[0] - mu, d1 = x[1] - mu, d2 = x[2] - mu, d3 = x[3] - mu;
    float ss = d0 * d0 + d1 * d1 + d2 * d2 + d3 * d3;
#pragma unroll
    for (int o = 16; o; o >>= 1) ss += __shfl_xor_sync(0xFFFFFFFFu, ss, o);
    if (!lane) sm2[w] = ss;
    __syncthreads();
    float var = (sm2[0] + sm2[1] + sm2[2] + sm2[3]) * (1.0f / 512.0f);
    float inv = rsqrtf(var + LN_EPS);

    float4 gg = ((const float4*)g)[tid];
    float4 bv = ((const float4*)bb)[tid];
    float4 o4;
    o4.x = d0 * inv * gg.x + bv.x;
    o4.y = d1 * inv * gg.y + bv.y;
    o4.z = d2 * inv * gg.z + bv.z;
    o4.w = d3 * inv * gg.w + bv.w;
    *(float4*)(out + base) = o4;
}

// ---------------------------------------------------------------------------
// Launch
// ---------------------------------------------------------------------------
extern "C" void kernel_launch(void* const* d_in, const int* in_sizes, int n_in,
                              void* d_out, int out_size) {
    const float* x    = (const float*)d_in[0];
    const float* Wq   = (const float*)d_in[1];
    const float* bq   = (const float*)d_in[2];
    const float* Wk   = (const float*)d_in[3];
    const float* bk   = (const float*)d_in[4];
    const float* Wv   = (const float*)d_in[5];
    const float* bv   = (const float*)d_in[6];
    const float* Wo   = (const float*)d_in[7];
    const float* bo   = (const float*)d_in[8];
    const float* ln1g = (const float*)d_in[9];
    const float* ln1b = (const float*)d_in[10];
    const float* W1   = (const float*)d_in[11];
    const float* b1   = (const float*)d_in[12];
    const float* W2   = (const float*)d_in[13];
    const float* b2   = (const float*)d_in[14];
    const float* ln2g = (const float*)d_in[15];
    const float* ln2b = (const float*)d_in[16];
    float* out = (float*)d_out;

    __nv_bfloat16 *h_hi, *h_lo, *qkv_hi, *qkv_lo, *ctx_hi, *ctx_lo,
                  *t_hi, *t_lo, *mid_hi, *mid_lo,
                  *sh_hi, *sh_lo, *qs_hi, *qs_lo,
                  *wqkvT_hi, *wqkvT_lo, *woT_hi, *woT_lo,
                  *w1T_hi, *w1T_lo, *w2T_hi, *w2T_lo;
    float* bqkv;
    cudaGetSymbolAddress((void**)&h_hi, g_h_hi);     cudaGetSymbolAddress((void**)&h_lo, g_h_lo);
    cudaGetSymbolAddress((void**)&qkv_hi, g_qkv_hi); cudaGetSymbolAddress((void**)&qkv_lo, g_qkv_lo);
    cudaGetSymbolAddress((void**)&ctx_hi, g_ctx_hi); cudaGetSymbolAddress((void**)&ctx_lo, g_ctx_lo);
    cudaGetSymbolAddress((void**)&t_hi, g_t_hi);     cudaGetSymbolAddress((void**)&t_lo, g_t_lo);
    cudaGetSymbolAddress((void**)&mid_hi, g_mid_hi); cudaGetSymbolAddress((void**)&mid_lo, g_mid_lo);
    cudaGetSymbolAddress((void**)&sh_hi, g_sh_hi);   cudaGetSymbolAddress((void**)&sh_lo, g_sh_lo);
    cudaGetSymbolAddress((void**)&qs_hi, g_qs_hi);   cudaGetSymbolAddress((void**)&qs_lo, g_qs_lo);
    cudaGetSymbolAddress((void**)&wqkvT_hi, g_wqkvT_hi); cudaGetSymbolAddress((void**)&wqkvT_lo, g_wqkvT_lo);
    cudaGetSymbolAddress((void**)&woT_hi, g_woT_hi); cudaGetSymbolAddress((void**)&woT_lo, g_woT_lo);
    cudaGetSymbolAddress((void**)&w1T_hi, g_w1T_hi); cudaGetSymbolAddress((void**)&w1T_lo, g_w1T_lo);
    cudaGetSymbolAddress((void**)&w2T_hi, g_w2T_hi); cudaGetSymbolAddress((void**)&w2T_lo, g_w2T_lo);
    cudaGetSymbolAddress((void**)&bqkv, g_bqkv);

    cudaFuncSetAttribute(gemm_wmma, cudaFuncAttributeMaxDynamicSharedMemorySize, GSMEM);

    const size_t WQKV = (size_t)DQKV * DM;
    const size_t WOO  = (size_t)DM * DM;
    const size_t W1S  = (size_t)DH * DM;
    const size_t W2S  = (size_t)DM * DH;

    // Launch 1: pos encode
    pos_kernel<<<(MTOK * DM) / 256, 256>>>(x, h_hi, h_lo);

    // Launches 2-5: ALL weight prep up front (so ncu -s 5 lands on gemm QKV)
    for (int l = 0; l < 2; l++) {
        const size_t oW  = (size_t)l * DM * DM;
        const size_t oV  = (size_t)l * DM;
        const size_t oW1 = (size_t)l * DM * DH;
        const size_t oW2 = (size_t)l * DH * DM;
        wprep_kernel<<<3072, 256>>>(
            Wq + oW, Wk + oW, Wv + oW, Wo + oW, W1 + oW1, W2 + oW2,
            wqkvT_hi + l * WQKV, wqkvT_lo + l * WQKV,
            woT_hi + l * WOO,    woT_lo + l * WOO,
            w1T_hi + l * W1S,    w1T_lo + l * W1S,
            w2T_hi + l * W2S,    w2T_lo + l * W2S);
        bcat_kernel<<<6, 256>>>(bq + oV, bk + oV, bv + oV, bqkv + l * DQKV);
    }

    // =========================== Layer 0 (full) ===========================
    {
        const int l = 0;
        const size_t oV  = (size_t)l * DM;
        const size_t oB1 = (size_t)l * DH;

        // Launch 6: QKV GEMM (ncu-profiled)
        gemm_wmma<<<dim3(DQKV / BN, MTOK / BM), 256, GSMEM>>>(
            h_hi, h_lo, wqkvT_hi + l * WQKV, wqkvT_lo + l * WQKV,
            bqkv + l * DQKV, qkv_hi, qkv_lo, DQKV, DM, 0);
        attn_kernel<<<BATCH, 256>>>(qkv_hi, qkv_lo, ctx_hi, ctx_lo);
        gemm_wmma<<<dim3(DM / BN, MTOK / BM), 256, GSMEM>>>(
            ctx_hi, ctx_lo, woT_hi + l * WOO, woT_lo + l * WOO,
            bo + oV, t_hi, t_lo, DM, DM, 0);
        ln_kernel<<<MTOK, 128>>>(t_hi, t_lo, h_hi, h_lo, ln1g + oV, ln1b + oV);
        gemm_wmma<<<dim3(DH / BN, MTOK / BM), 256, GSMEM>>>(
            h_hi, h_lo, w1T_hi + l * W1S, w1T_lo + l * W1S,
            b1 + oB1, mid_hi, mid_lo, DH, DM, 1);
        gemm_wmma<<<dim3(DM / BN, MTOK / BM), 256, GSMEM>>>(
            mid_hi, mid_lo, w2T_hi + l * W2S, w2T_lo + l * W2S,
            b2 + oV, t_hi, t_lo, DM, DH, 0);
        ln_kernel<<<MTOK, 128>>>(t_hi, t_lo, h_hi, h_lo, ln2g + oV, ln2b + oV);
    }

    // =================== Layer 1 (selected-token compact) ===================
    {
        const int l = 1;
        const size_t oV  = (size_t)l * DM;
        const size_t oB1 = (size_t)l * DH;

        // KV projection over ALL tokens: [M,512] @ [512,1024] (qkvT rows 512..1535)
        gemm_wmma<<<dim3(1024 / BN, MTOK / BM), 256, GSMEM>>>(
            h_hi, h_lo,
            wqkvT_hi + l * WQKV + (size_t)512 * DM,
            wqkvT_lo + l * WQKV + (size_t)512 * DM,
            bqkv + l * DQKV + 512, qkv_hi, qkv_lo, 1024, DM, 0);

        // gather selected rows of h, project Q only for those
        selgather_kernel<<<(MSEL * DM) / 256, 256>>>(h_hi, h_lo, sh_hi, sh_lo);
        gemm_wmma<<<dim3(DM / BN, MSEL / BM), 256, GSMEM>>>(
            sh_hi, sh_lo, wqkvT_hi + l * WQKV, wqkvT_lo + l * WQKV,
            bqkv + l * DQKV, qs_hi, qs_lo, DM, DM, 0);

        // 1-query attention per batch
        attn_sel_kernel<<<BATCH, 256>>>(qs_hi, qs_lo, qkv_hi, qkv_lo, ctx_hi, ctx_lo);

        // O-projection + LN1 on 16384 rows
        gemm_wmma<<<dim3(DM / BN, MSEL / BM), 256, GSMEM>>>(
            ctx_hi, ctx_lo, woT_hi + l * WOO, woT_lo + l * WOO,
            bo + oV, t_hi, t_lo, DM, DM, 0);
        ln_kernel<<<MSEL, 128>>>(t_hi, t_lo, sh_hi, sh_lo, ln1g + oV, ln1b + oV);

        // FFN on 16384 rows, final LN2 -> fp32 out (gather already applied)
        gemm_wmma<<<dim3(DH / BN, MSEL / BM), 256, GSMEM>>>(
            sh_hi, sh_lo, w1T_hi + l * W1S, w1T_lo + l * W1S,
            b1 + oB1, mid_hi, mid_lo, DH, DM, 1);
        gemm_wmma<<<dim3(DM / BN, MSEL / BM), 256, GSMEM>>>(
            mid_hi, mid_lo, w2T_hi + l * W2S, w2T_lo + l * W2S,
            b2 + oV, t_hi, t_lo, DM, DH, 0);
        lnout_kernel<<<MSEL, 128>>>(t_hi, t_lo, sh_hi, sh_lo, ln2g + oV, ln2b + oV, out);
    }
}